// round 4
// baseline (speedup 1.0000x reference)
#include <cuda_runtime.h>
#include <cuda_bf16.h>
#include <cstdint>

// Problem constants
#define Bc    4
#define Tc    2048
#define DINc  2048
#define Hc    2048
#define Ec    8
#define RANKc 64
#define NANCH 512
#define SCALING 0.25f

// GEMM tiling
#define TM 128
#define TN 128
#define KCF 64                       // fp32 K per chunk (64 int8 per limb, 128B rows)
#define NCHUNK (DINc / KCF)          // 32
#define MTILES ((Bc * Tc) / TM)      // 64
#define NTILES (Hc / TN)             // 16
#define TILE_B 16384                 // 128 rows x 128B ([limb1 64B | limb2 64B])
#define STAGE_B (2 * TILE_B)         // A tile + B tile
#define SMEM_TOTAL (2 * STAGE_B)     // 65536

__device__ float g_scale;
__device__ __align__(16) float g_pmix[Bc * NANCH * RANKc];
__device__ int g_xmax_i;
__device__ int g_wmax_i;
__device__ __align__(16) char g_qA[(size_t)MTILES * NCHUNK * TILE_B]; // 33.5MB
__device__ __align__(16) char g_qB[(size_t)NTILES * NCHUNK * TILE_B]; //  8.4MB

// ---------------------------------------------------------------------------
// Helpers
// ---------------------------------------------------------------------------
__device__ __forceinline__ uint32_t smem_u32(const void* p) {
    uint32_t a;
    asm("{ .reg .u64 t; cvta.to.shared.u64 t, %1; cvt.u32.u64 %0, t; }" : "=r"(a) : "l"(p));
    return a;
}
__device__ __forceinline__ uint32_t sw128(uint32_t off) { return off ^ ((off >> 3) & 0x70); }

__device__ __forceinline__ void ldmx4(uint32_t* r, uint32_t addr) {
    asm volatile("ldmatrix.sync.aligned.m8n8.x4.shared.b16 {%0,%1,%2,%3}, [%4];"
                 : "=r"(r[0]), "=r"(r[1]), "=r"(r[2]), "=r"(r[3]) : "r"(addr));
}
__device__ __forceinline__ void imma(int* c, const uint32_t* a, uint32_t b0, uint32_t b1) {
    asm volatile(
        "mma.sync.aligned.m16n8k32.row.col.s32.s8.s8.s32 "
        "{%0,%1,%2,%3},{%4,%5,%6,%7},{%8,%9},{%0,%1,%2,%3};"
        : "+r"(c[0]), "+r"(c[1]), "+r"(c[2]), "+r"(c[3])
        : "r"(a[0]), "r"(a[1]), "r"(a[2]), "r"(a[3]), "r"(b0), "r"(b1));
}
__device__ __forceinline__ void cp_async16(uint32_t dst, const void* src) {
    asm volatile("cp.async.cg.shared.global [%0], [%1], 16;" :: "r"(dst), "l"(src) : "memory");
}
#define CP_COMMIT() asm volatile("cp.async.commit_group;" ::: "memory")
#define CP_WAIT0()  asm volatile("cp.async.wait_group 0;" ::: "memory")

// ---------------------------------------------------------------------------
// Kernel 0: reset scales
// ---------------------------------------------------------------------------
__global__ void zero_scales_kernel() {
    if (threadIdx.x == 0) { g_xmax_i = 0; g_wmax_i = 0; }
}

// ---------------------------------------------------------------------------
// Kernel A: absmax over a float array (deterministic: atomicMax on float bits)
// ---------------------------------------------------------------------------
__global__ __launch_bounds__(256) void absmax_arr_kernel(
    const float4* __restrict__ p, int n4, int* __restrict__ out)
{
    __shared__ int red[256];
    float m = 0.0f;
    for (int i = blockIdx.x * 256 + threadIdx.x; i < n4; i += gridDim.x * 256) {
        float4 v = p[i];
        m = fmaxf(m, fmaxf(fmaxf(fabsf(v.x), fabsf(v.y)), fmaxf(fabsf(v.z), fabsf(v.w))));
    }
    red[threadIdx.x] = __float_as_int(m);
    __syncthreads();
    for (int s = 128; s > 0; s >>= 1) {
        if (threadIdx.x < s) red[threadIdx.x] = max(red[threadIdx.x], red[threadIdx.x + s]);
        __syncthreads();
    }
    if (threadIdx.x == 0) atomicMax(out, red[0]);
}

// ---------------------------------------------------------------------------
// Kernel B: quantize fp32 -> two s8 limbs, tile-major layout
// dst[tile][chunk][row][128B]: bytes 0-63 limb1, 64-127 limb2.
// One thread per float4 (4 k-elements).
// ---------------------------------------------------------------------------
__global__ __launch_bounds__(256) void quant_kernel(
    const float* __restrict__ src, char* __restrict__ dst,
    const int* __restrict__ maxbits)
{
    const float inv = 127.0f / __int_as_float(*maxbits);
    int lin  = blockIdx.x * 256 + threadIdx.x;
    int i4   = lin & 15;
    int row  = (lin >> 4) & 127;
    int chunk= (lin >> 11) & 31;
    int tile = lin >> 16;

    const float4 v = *(const float4*)(src +
        ((size_t)(tile * 128 + row)) * DINc + chunk * 64 + i4 * 4);

    int h0 = __float2int_rn(v.x * inv); int l0 = __float2int_rn((v.x * inv - h0) * 128.0f);
    int h1 = __float2int_rn(v.y * inv); int l1 = __float2int_rn((v.y * inv - h1) * 128.0f);
    int h2 = __float2int_rn(v.z * inv); int l2 = __float2int_rn((v.z * inv - h2) * 128.0f);
    int h3 = __float2int_rn(v.w * inv); int l3 = __float2int_rn((v.w * inv - h3) * 128.0f);

    uint32_t hp = (h0 & 255) | ((h1 & 255) << 8) | ((h2 & 255) << 16) | ((uint32_t)(h3 & 255) << 24);
    uint32_t lp = (l0 & 255) | ((l1 & 255) << 8) | ((l2 & 255) << 16) | ((uint32_t)(l3 & 255) << 24);

    char* base = dst + (((size_t)(tile * NCHUNK + chunk)) << 14) + (row << 7) + (i4 << 2);
    *(uint32_t*)(base)      = hp;
    *(uint32_t*)(base + 64) = lp;
}

// ---------------------------------------------------------------------------
// Kernel 1: 2-limb int8 IMMA GEMM   C = x @ W^T + b
// 128x128 tile, 8 warps (2x4, each 64x32), double-buffered cp.async.
// C = sx*sw*(S11 + Smix/128) + bias
// ---------------------------------------------------------------------------
__global__ __launch_bounds__(256) void gemm_imma_kernel(
    const float* __restrict__ bias, float* __restrict__ C)
{
    extern __shared__ char smem[];
    const uint32_t sbase = smem_u32(smem);
    const int tid    = threadIdx.x;
    const int lane   = tid & 31;
    const int wid    = tid >> 5;
    const int warp_m = wid >> 2;
    const int warp_n = wid & 3;
    const int bx = blockIdx.x, by = blockIdx.y;

    const char* gA = g_qA + ((size_t)by * NCHUNK << 14);
    const char* gB = g_qB + ((size_t)bx * NCHUNK << 14);

    int s11[4][4][4], smix[4][4][4];
    #pragma unroll
    for (int i = 0; i < 4; i++)
        #pragma unroll
        for (int j = 0; j < 4; j++)
            #pragma unroll
            for (int k = 0; k < 4; k++) { s11[i][j][k] = 0; smix[i][j][k] = 0; }

    const int a_row_base = warp_m * 64 + (lane & 15);
    const int a_chunk    = (lane >> 4) << 4;
    const int b_row_base = warp_n * 32 + (((lane >> 4) & 1) << 3) + (lane & 7);
    const int b_chunk    = ((lane >> 3) & 1) << 4;

    // cp.async loader: 4x16B for A, 4x16B for B per thread per chunk
    auto load_chunk = [&](int c, int stage) {
        const uint32_t stg = sbase + stage * STAGE_B;
        const char* srcA = gA + ((size_t)c << 14);
        const char* srcB = gB + ((size_t)c << 14);
        #pragma unroll
        for (int p = 0; p < 4; p++) {
            uint32_t off = (uint32_t)(tid * 64 + p * 16);
            cp_async16(stg + sw128(off), srcA + off);
            cp_async16(stg + TILE_B + sw128(off), srcB + off);
        }
        CP_COMMIT();
    };

    auto compute = [&](int stage) {
        const uint32_t sa = sbase + stage * STAGE_B;
        const uint32_t sb = sa + TILE_B;
        #pragma unroll
        for (int ks = 0; ks < 2; ks++) {
            uint32_t a1[4][4], a2[4][4];
            #pragma unroll
            for (int mt = 0; mt < 4; mt++) {
                uint32_t ro = (uint32_t)((a_row_base + mt * 16) * 128 + ks * 32 + a_chunk);
                ldmx4(a1[mt], sa + sw128(ro));
                ldmx4(a2[mt], sa + sw128(ro + 64));
            }
            uint32_t b1[2][4], b2[2][4];
            #pragma unroll
            for (int nt2 = 0; nt2 < 2; nt2++) {
                uint32_t ro = (uint32_t)((b_row_base + nt2 * 16) * 128 + ks * 32 + b_chunk);
                ldmx4(b1[nt2], sb + sw128(ro));
                ldmx4(b2[nt2], sb + sw128(ro + 64));
            }
            #pragma unroll
            for (int mt = 0; mt < 4; mt++)
                #pragma unroll
                for (int nt = 0; nt < 4; nt++) {
                    uint32_t w10 = b1[nt >> 1][(nt & 1) * 2], w11 = b1[nt >> 1][(nt & 1) * 2 + 1];
                    uint32_t w20 = b2[nt >> 1][(nt & 1) * 2], w21 = b2[nt >> 1][(nt & 1) * 2 + 1];
                    imma(s11[mt][nt],  a1[mt], w10, w11);
                    imma(smix[mt][nt], a1[mt], w20, w21);
                    imma(smix[mt][nt], a2[mt], w10, w11);
                }
        }
    };

    load_chunk(0, 0);
    for (int c = 0; c < NCHUNK; c++) {
        CP_WAIT0();
        __syncthreads();
        if (c + 1 < NCHUNK) load_chunk(c + 1, (c + 1) & 1);
        compute(c & 1);
        __syncthreads();
    }

    // Epilogue
    const float xm = __int_as_float(g_xmax_i);
    const float wm = __int_as_float(g_wmax_i);
    const float s  = xm * wm * (1.0f / 16129.0f);   // (xm/127)*(wm/127)

    const int row0 = by * TM + warp_m * 64;
    const int col0 = bx * TN + warp_n * 32;
    #pragma unroll
    for (int mt = 0; mt < 4; mt++) {
        int r = row0 + mt * 16 + (lane >> 2);
        #pragma unroll
        for (int nt = 0; nt < 4; nt++) {
            int cc = col0 + nt * 8 + (lane & 3) * 2;
            float b0 = bias[cc], b1v = bias[cc + 1];
            const int* S = s11[mt][nt];
            const int* X = smix[mt][nt];
            float f0 = (float)S[0] + (float)X[0] * 0.0078125f;
            float f1 = (float)S[1] + (float)X[1] * 0.0078125f;
            float f2 = (float)S[2] + (float)X[2] * 0.0078125f;
            float f3 = (float)S[3] + (float)X[3] * 0.0078125f;
            float2 o0 = make_float2(f0 * s + b0, f1 * s + b1v);
            float2 o1 = make_float2(f2 * s + b0, f3 * s + b1v);
            *(float2*)(C + (size_t)r * Hc + cc)       = o0;
            *(float2*)(C + (size_t)(r + 8) * Hc + cc) = o1;
        }
    }
}

// ---------------------------------------------------------------------------
// Kernel 2: global abs-max over Hs = base[:, anchors, :E]
// ---------------------------------------------------------------------------
__global__ __launch_bounds__(256) void absmax_kernel(const float* __restrict__ C)
{
    __shared__ float red[256];
    float m = 0.0f;
    for (int i = threadIdx.x; i < Bc * NANCH * Ec; i += 256) {
        int b    = i >> 12;
        int rest = i & 4095;
        int a    = rest >> 3;
        int e    = rest & 7;
        int t    = a * 4 + 3;
        float v  = C[((size_t)(b * Tc + t)) * Hc + e];
        m = fmaxf(m, fabsf(v));
    }
    red[threadIdx.x] = m;
    __syncthreads();
    for (int s = 128; s > 0; s >>= 1) {
        if (threadIdx.x < s)
            red[threadIdx.x] = fmaxf(red[threadIdx.x], red[threadIdx.x + s]);
        __syncthreads();
    }
    if (threadIdx.x == 0) g_scale = fmaxf(red[0], 1e-6f);
}

// ---------------------------------------------------------------------------
// Kernel 3: softmax / top-2 soft mask / w @ LiMEs -> g_pmix
// ---------------------------------------------------------------------------
__global__ __launch_bounds__(256) void pmix_kernel(
    const float* __restrict__ C, const float* __restrict__ L)
{
    __shared__ float sL[Ec * RANKc];
    for (int i = threadIdx.x; i < Ec * RANKc; i += 256) sL[i] = L[i];
    __syncthreads();

    int idx = blockIdx.x * 256 + threadIdx.x;
    int b   = idx >> 9;
    int a   = idx & (NANCH - 1);
    int t   = a * 4 + 3;
    const float* h = C + ((size_t)(b * Tc + t)) * Hc;

    float inv_scale = 1.0f / g_scale;

    float l[Ec], lmax = -1e30f;
    #pragma unroll
    for (int e = 0; e < Ec; e++) {
        l[e] = h[e] * inv_scale;
        lmax = fmaxf(lmax, l[e]);
    }
    float p[Ec], s = 0.0f;
    #pragma unroll
    for (int e = 0; e < Ec; e++) { p[e] = expf(l[e] - lmax); s += p[e]; }
    float invs = 1.0f / s;
    #pragma unroll
    for (int e = 0; e < Ec; e++) p[e] *= invs;

    float m1 = -1e30f, m2 = -1e30f;
    #pragma unroll
    for (int e = 0; e < Ec; e++) {
        float v = p[e];
        if (v > m1) { m2 = m1; m1 = v; }
        else if (v > m2) { m2 = v; }
    }
    float w[Ec], ws = 0.0f;
    #pragma unroll
    for (int e = 0; e < Ec; e++) {
        float mask = 1.0f / (1.0f + expf(-(p[e] - m2) * 2.0f));
        w[e] = p[e] * mask;
        ws  += w[e];
    }
    float invws = 1.0f / (ws + 1e-9f);

    float* out = g_pmix + (size_t)idx * RANKc;
    #pragma unroll 8
    for (int r = 0; r < RANKc; r++) {
        float acc = 0.0f;
        #pragma unroll
        for (int e = 0; e < Ec; e++) acc += w[e] * sL[e * RANKc + r];
        out[r] = acc * invws;
    }
}

// ---------------------------------------------------------------------------
// Kernel 4: out[..., :RANK] *= (1 + SCALING * p_mix_full)
// ---------------------------------------------------------------------------
__global__ __launch_bounds__(256) void apply_kernel(float* __restrict__ C)
{
    int idx = blockIdx.x * blockDim.x + threadIdx.x;
    int r4  = idx & 15;
    int tg  = idx >> 4;
    int t   = tg & (Tc - 1);
    int b   = tg >> 11;
    int a   = t >> 2;

    const float4 p = ((const float4*)g_pmix)[((b << 9) + a) * 16 + r4];
    float4* cp = (float4*)(C + (size_t)tg * Hc) + r4;
    float4 v = *cp;
    v.x *= 1.0f + SCALING * p.x;
    v.y *= 1.0f + SCALING * p.y;
    v.z *= 1.0f + SCALING * p.z;
    v.w *= 1.0f + SCALING * p.w;
    *cp = v;
}

// ---------------------------------------------------------------------------
extern "C" void kernel_launch(void* const* d_in, const int* in_sizes, int n_in,
                              void* d_out, int out_size)
{
    const float* x = (const float*)d_in[0];   // [B*T, DIN]
    const float* W = (const float*)d_in[1];   // [H, DIN]
    const float* b = (const float*)d_in[2];   // [H]
    const float* L = (const float*)d_in[3];   // [E, RANK]
    float* out = (float*)d_out;

    cudaFuncSetAttribute(gemm_imma_kernel,
                         cudaFuncAttributeMaxDynamicSharedMemorySize, SMEM_TOTAL);

    int* xmax_p; cudaGetSymbolAddress((void**)&xmax_p, g_xmax_i);
    int* wmax_p; cudaGetSymbolAddress((void**)&wmax_p, g_wmax_i);
    char* qA_p;  cudaGetSymbolAddress((void**)&qA_p, g_qA);
    char* qB_p;  cudaGetSymbolAddress((void**)&qB_p, g_qB);

    zero_scales_kernel<<<1, 32>>>();
    absmax_arr_kernel<<<2048, 256>>>((const float4*)x, (Bc * Tc * DINc) / 4, xmax_p);
    absmax_arr_kernel<<<1024, 256>>>((const float4*)W, (Hc * DINc) / 4, wmax_p);
    quant_kernel<<<(MTILES * NCHUNK * 128 * 16) / 256, 256>>>(x, qA_p, xmax_p);
    quant_kernel<<<(NTILES * NCHUNK * 128 * 16) / 256, 256>>>(W, qB_p, wmax_p);

    dim3 grid(NTILES, MTILES);   // (16, 64)
    gemm_imma_kernel<<<grid, 256, SMEM_TOTAL>>>(b, out);
    absmax_kernel<<<1, 256>>>(out);
    pmix_kernel<<<(Bc * NANCH) / 256, 256>>>(out, L);
    apply_kernel<<<(Bc * Tc * 16) / 256, 256>>>(out);
}

// round 5
// speedup vs baseline: 3.9680x; 3.9680x over previous
#include <cuda_runtime.h>
#include <cuda_bf16.h>
#include <cstdint>

// Problem constants
#define Bc    4
#define Tc    2048
#define DINc  2048
#define Hc    2048
#define Ec    8
#define RANKc 64
#define NANCH 512
#define SCALING 0.25f

// GEMM tiling
#define TM 128
#define TN 128
#define KC 64                          // fp32 K per chunk
#define NCHUNK (DINc / KC)             // 32
#define MTILES ((Bc * Tc) / TM)        // 64
#define NTILES (Hc / TN)               // 16
#define FRAGS_PER_CHUNK 2048           // (8 ksteps)*(8 blk16)*(32 lanes) float4 frags
#define ACH_B  (FRAGS_PER_CHUNK * 16)  // 32768 bytes per operand per chunk
#define STAGE_B (2 * ACH_B)            // 65536
#define SMEM_TOTAL (2 * STAGE_B)       // 131072

__device__ float g_scale;
__device__ __align__(16) float g_pmix[Bc * NANCH * RANKc];
// Fragment-ordered tf32 copies: A 64MB, B 16MB
__device__ __align__(16) float4 g_fA[(size_t)MTILES * NCHUNK * FRAGS_PER_CHUNK];
__device__ __align__(16) float4 g_fB[(size_t)NTILES * NCHUNK * FRAGS_PER_CHUNK];

// ---------------------------------------------------------------------------
// Helpers
// ---------------------------------------------------------------------------
__device__ __forceinline__ uint32_t smem_u32(const void* p) {
    uint32_t a;
    asm("{ .reg .u64 t; cvta.to.shared.u64 t, %1; cvt.u32.u64 %0, t; }" : "=r"(a) : "l"(p));
    return a;
}
__device__ __forceinline__ float to_tf32(float x) {
    float r;
    asm("cvt.rna.tf32.f32 %0, %1;" : "=f"(r) : "f"(x));
    return r;
}
__device__ __forceinline__ void lds128(float4& v, uint32_t addr) {
    asm volatile("ld.shared.v4.f32 {%0,%1,%2,%3}, [%4];"
                 : "=f"(v.x), "=f"(v.y), "=f"(v.z), "=f"(v.w) : "r"(addr));
}
__device__ __forceinline__ void mma_tf32(float* c, const float4& a, float b0, float b1) {
    asm volatile(
        "mma.sync.aligned.m16n8k8.row.col.f32.tf32.tf32.f32 "
        "{%0,%1,%2,%3},{%4,%5,%6,%7},{%8,%9},{%0,%1,%2,%3};"
        : "+f"(c[0]), "+f"(c[1]), "+f"(c[2]), "+f"(c[3])
        : "r"(__float_as_uint(a.x)), "r"(__float_as_uint(a.y)),
          "r"(__float_as_uint(a.z)), "r"(__float_as_uint(a.w)),
          "r"(__float_as_uint(b0)),  "r"(__float_as_uint(b1)));
}
__device__ __forceinline__ void cp_async16(uint32_t dst, const void* src) {
    asm volatile("cp.async.cg.shared.global [%0], [%1], 16;" :: "r"(dst), "l"(src) : "memory");
}
#define CP_COMMIT() asm volatile("cp.async.commit_group;" ::: "memory")
#define CP_WAIT0()  asm volatile("cp.async.wait_group 0;" ::: "memory")

// ---------------------------------------------------------------------------
// Pack kernels: fp32 [rows, DIN] -> tf32 fragment order
// A frag float4 = {A[r,k], A[r+8,k], A[r,k+4], A[r+8,k+4]}  (a0,a1,a2,a3)
// B frag float4 = {W[n,k], W[n,k+4], W[n+8,k], W[n+8,k+4]}  (b0,b1 | b0',b1')
// index t -> lane=t&31, blk16=(t>>5)&7, ks=(t>>8)&7, c=(t>>11)&31, tile=t>>16
// ---------------------------------------------------------------------------
__global__ __launch_bounds__(256) void pack_A_kernel(
    const float* __restrict__ src, float4* __restrict__ dst)
{
    int t    = blockIdx.x * 256 + threadIdx.x;
    int lane = t & 31;
    int m16  = (t >> 5) & 7;
    int ks   = (t >> 8) & 7;
    int c    = (t >> 11) & 31;
    int tile = t >> 16;
    int gr = tile * 128 + m16 * 16 + (lane >> 2);
    int gk = c * 64 + ks * 8 + (lane & 3);
    const float* p0 = src + (size_t)gr * DINc + gk;
    const float* p1 = p0 + 8 * DINc;
    float4 v;
    v.x = to_tf32(p0[0]);
    v.y = to_tf32(p1[0]);
    v.z = to_tf32(p0[4]);
    v.w = to_tf32(p1[4]);
    dst[t] = v;
}
__global__ __launch_bounds__(256) void pack_B_kernel(
    const float* __restrict__ src, float4* __restrict__ dst)
{
    int t    = blockIdx.x * 256 + threadIdx.x;
    int lane = t & 31;
    int n16  = (t >> 5) & 7;
    int ks   = (t >> 8) & 7;
    int c    = (t >> 11) & 31;
    int tile = t >> 16;
    int gn = tile * 128 + n16 * 16 + (lane >> 2);
    int gk = c * 64 + ks * 8 + (lane & 3);
    const float* p0 = src + (size_t)gn * DINc + gk;
    const float* p1 = p0 + 8 * DINc;
    float4 v;
    v.x = to_tf32(p0[0]);
    v.y = to_tf32(p0[4]);
    v.z = to_tf32(p1[0]);
    v.w = to_tf32(p1[4]);
    dst[t] = v;
}

// ---------------------------------------------------------------------------
// Kernel 1: single-pass tf32 mma GEMM   C = x @ W^T + b
// 128x128 tile, 16 warps (4x4, each 32x32), double-buffered cp.async,
// fragment-ordered SMEM -> lds.128 only.
// ---------------------------------------------------------------------------
__global__ __launch_bounds__(512) void gemm_tf32_kernel(
    const float* __restrict__ bias, float* __restrict__ C)
{
    extern __shared__ char smem[];
    const uint32_t sbase = smem_u32(smem);
    const int tid    = threadIdx.x;
    const int lane   = tid & 31;
    const int wid    = tid >> 5;
    const int warp_m = wid >> 2;      // 0..3 -> rows *32
    const int warp_n = wid & 3;       // 0..3 -> cols *32
    const int bx = blockIdx.x, by = blockIdx.y;

    const float4* gA = g_fA + (size_t)by * NCHUNK * FRAGS_PER_CHUNK;
    const float4* gB = g_fB + (size_t)bx * NCHUNK * FRAGS_PER_CHUNK;

    float acc[2][4][4];
    #pragma unroll
    for (int i = 0; i < 2; i++)
        #pragma unroll
        for (int j = 0; j < 4; j++)
            #pragma unroll
            for (int k = 0; k < 4; k++) acc[i][j][k] = 0.0f;

    auto load_chunk = [&](int c, int st) {
        const uint32_t base = sbase + st * STAGE_B;
        const float4* sA = gA + c * FRAGS_PER_CHUNK;
        const float4* sB = gB + c * FRAGS_PER_CHUNK;
        #pragma unroll
        for (int p = 0; p < 4; p++) {
            int idx = p * 512 + tid;
            cp_async16(base + idx * 16, sA + idx);
            cp_async16(base + ACH_B + idx * 16, sB + idx);
        }
        CP_COMMIT();
    };

    auto compute = [&](int st) {
        const uint32_t sa = sbase + st * STAGE_B;
        const uint32_t sb = sa + ACH_B;
        #pragma unroll
        for (int ks = 0; ks < 8; ks++) {
            float4 va[2], vb[2];
            #pragma unroll
            for (int mt = 0; mt < 2; mt++) {
                int m16 = warp_m * 2 + mt;
                lds128(va[mt], sa + ((ks * 8 + m16) * 32 + lane) * 16);
            }
            #pragma unroll
            for (int j = 0; j < 2; j++) {
                int n16 = warp_n * 2 + j;
                lds128(vb[j], sb + ((ks * 8 + n16) * 32 + lane) * 16);
            }
            #pragma unroll
            for (int mt = 0; mt < 2; mt++)
                #pragma unroll
                for (int j = 0; j < 2; j++) {
                    mma_tf32(acc[mt][2 * j],     va[mt], vb[j].x, vb[j].y);
                    mma_tf32(acc[mt][2 * j + 1], va[mt], vb[j].z, vb[j].w);
                }
        }
    };

    load_chunk(0, 0);
    for (int c = 0; c < NCHUNK; c++) {
        CP_WAIT0();
        __syncthreads();
        if (c + 1 < NCHUNK) load_chunk(c + 1, (c + 1) & 1);
        compute(c & 1);
        __syncthreads();
    }

    // Epilogue: c0/c1 at (row, 2*(lane&3)), c2/c3 at row+8
    const int row0 = by * TM + warp_m * 32;
    const int col0 = bx * TN + warp_n * 32;
    #pragma unroll
    for (int mt = 0; mt < 2; mt++) {
        int r = row0 + mt * 16 + (lane >> 2);
        #pragma unroll
        for (int nt = 0; nt < 4; nt++) {
            int cc = col0 + nt * 8 + (lane & 3) * 2;
            float b0 = bias[cc], b1 = bias[cc + 1];
            const float* a = acc[mt][nt];
            *(float2*)(C + (size_t)r * Hc + cc)       = make_float2(a[0] + b0, a[1] + b1);
            *(float2*)(C + (size_t)(r + 8) * Hc + cc) = make_float2(a[2] + b0, a[3] + b1);
        }
    }
}

// ---------------------------------------------------------------------------
// Kernel 2: global abs-max over Hs = base[:, anchors, :E]
// ---------------------------------------------------------------------------
__global__ __launch_bounds__(256) void absmax_kernel(const float* __restrict__ C)
{
    __shared__ float red[256];
    float m = 0.0f;
    for (int i = threadIdx.x; i < Bc * NANCH * Ec; i += 256) {
        int b    = i >> 12;
        int rest = i & 4095;
        int a    = rest >> 3;
        int e    = rest & 7;
        int t    = a * 4 + 3;
        float v  = C[((size_t)(b * Tc + t)) * Hc + e];
        m = fmaxf(m, fabsf(v));
    }
    red[threadIdx.x] = m;
    __syncthreads();
    for (int s = 128; s > 0; s >>= 1) {
        if (threadIdx.x < s)
            red[threadIdx.x] = fmaxf(red[threadIdx.x], red[threadIdx.x + s]);
        __syncthreads();
    }
    if (threadIdx.x == 0) g_scale = fmaxf(red[0], 1e-6f);
}

// ---------------------------------------------------------------------------
// Kernel 3: softmax / top-2 soft mask / w @ LiMEs -> g_pmix
// ---------------------------------------------------------------------------
__global__ __launch_bounds__(256) void pmix_kernel(
    const float* __restrict__ C, const float* __restrict__ L)
{
    __shared__ float sL[Ec * RANKc];
    for (int i = threadIdx.x; i < Ec * RANKc; i += 256) sL[i] = L[i];
    __syncthreads();

    int idx = blockIdx.x * 256 + threadIdx.x;
    int b   = idx >> 9;
    int a   = idx & (NANCH - 1);
    int t   = a * 4 + 3;
    const float* h = C + ((size_t)(b * Tc + t)) * Hc;

    float inv_scale = 1.0f / g_scale;

    float l[Ec], lmax = -1e30f;
    #pragma unroll
    for (int e = 0; e < Ec; e++) {
        l[e] = h[e] * inv_scale;
        lmax = fmaxf(lmax, l[e]);
    }
    float p[Ec], s = 0.0f;
    #pragma unroll
    for (int e = 0; e < Ec; e++) { p[e] = expf(l[e] - lmax); s += p[e]; }
    float invs = 1.0f / s;
    #pragma unroll
    for (int e = 0; e < Ec; e++) p[e] *= invs;

    float m1 = -1e30f, m2 = -1e30f;
    #pragma unroll
    for (int e = 0; e < Ec; e++) {
        float v = p[e];
        if (v > m1) { m2 = m1; m1 = v; }
        else if (v > m2) { m2 = v; }
    }
    float w[Ec], ws = 0.0f;
    #pragma unroll
    for (int e = 0; e < Ec; e++) {
        float mask = 1.0f / (1.0f + expf(-(p[e] - m2) * 2.0f));
        w[e] = p[e] * mask;
        ws  += w[e];
    }
    float invws = 1.0f / (ws + 1e-9f);

    float* out = g_pmix + (size_t)idx * RANKc;
    #pragma unroll 8
    for (int r = 0; r < RANKc; r++) {
        float acc = 0.0f;
        #pragma unroll
        for (int e = 0; e < Ec; e++) acc += w[e] * sL[e * RANKc + r];
        out[r] = acc * invws;
    }
}

// ---------------------------------------------------------------------------
// Kernel 4: out[..., :RANK] *= (1 + SCALING * p_mix_full)
// ---------------------------------------------------------------------------
__global__ __launch_bounds__(256) void apply_kernel(float* __restrict__ C)
{
    int idx = blockIdx.x * blockDim.x + threadIdx.x;
    int r4  = idx & 15;
    int tg  = idx >> 4;
    int t   = tg & (Tc - 1);
    int b   = tg >> 11;
    int a   = t >> 2;

    const float4 p = ((const float4*)g_pmix)[((b << 9) + a) * 16 + r4];
    float4* cp = (float4*)(C + (size_t)tg * Hc) + r4;
    float4 v = *cp;
    v.x *= 1.0f + SCALING * p.x;
    v.y *= 1.0f + SCALING * p.y;
    v.z *= 1.0f + SCALING * p.z;
    v.w *= 1.0f + SCALING * p.w;
    *cp = v;
}

// ---------------------------------------------------------------------------
extern "C" void kernel_launch(void* const* d_in, const int* in_sizes, int n_in,
                              void* d_out, int out_size)
{
    const float* x = (const float*)d_in[0];   // [B*T, DIN]
    const float* W = (const float*)d_in[1];   // [H, DIN]
    const float* b = (const float*)d_in[2];   // [H]
    const float* L = (const float*)d_in[3];   // [E, RANK]
    float* out = (float*)d_out;

    cudaFuncSetAttribute(gemm_tf32_kernel,
                         cudaFuncAttributeMaxDynamicSharedMemorySize, SMEM_TOTAL);

    float4* fA_p; cudaGetSymbolAddress((void**)&fA_p, g_fA);
    float4* fB_p; cudaGetSymbolAddress((void**)&fB_p, g_fB);

    pack_A_kernel<<<(MTILES * NCHUNK * FRAGS_PER_CHUNK) / 256, 256>>>(x, fA_p);
    pack_B_kernel<<<(NTILES * NCHUNK * FRAGS_PER_CHUNK) / 256, 256>>>(W, fB_p);

    dim3 grid(NTILES, MTILES);   // (16, 64)
    gemm_tf32_kernel<<<grid, 512, SMEM_TOTAL>>>(b, out);
    absmax_kernel<<<1, 256>>>(out);
    pmix_kernel<<<(Bc * NANCH) / 256, 256>>>(out, L);
    apply_kernel<<<(Bc * Tc * 16) / 256, 256>>>(out);
}

// round 6
// speedup vs baseline: 7.2411x; 1.8249x over previous
#include <cuda_runtime.h>
#include <cuda_fp16.h>
#include <cstdint>

// Problem constants
#define Bc    4
#define Tc    2048
#define DINc  2048
#define Hc    2048
#define Ec    8
#define RANKc 64
#define NANCH 512
#define SCALING 0.25f

// GEMM tiling
#define TM 128
#define TN 128
#define KC 64                          // fp32 K per chunk
#define NCHUNK (DINc / KC)             // 32
#define MTILES ((Bc * Tc) / TM)        // 64
#define NTILES (Hc / TN)               // 16
#define FRAGS_PER_CHUNK 1024           // (4 ksteps)*(8 blk16)*(32 lanes) uint4 frags
#define ACH_B  (FRAGS_PER_CHUNK * 16)  // 16384 bytes per operand per chunk
#define STAGE_B (2 * ACH_B)            // 32768
#define NSTAGE 3
#define SMEM_TOTAL (NSTAGE * STAGE_B)  // 98304

__device__ int g_scale_i;
__device__ __align__(16) float g_pmix[Bc * NANCH * RANKc];
// Fragment-ordered fp16 copies: A 32MB, B 8MB
__device__ __align__(16) uint4 g_fA[(size_t)MTILES * NCHUNK * FRAGS_PER_CHUNK];
__device__ __align__(16) uint4 g_fB[(size_t)NTILES * NCHUNK * FRAGS_PER_CHUNK];

// ---------------------------------------------------------------------------
// Helpers
// ---------------------------------------------------------------------------
__device__ __forceinline__ uint32_t smem_u32(const void* p) {
    uint32_t a;
    asm("{ .reg .u64 t; cvta.to.shared.u64 t, %1; cvt.u32.u64 %0, t; }" : "=r"(a) : "l"(p));
    return a;
}
__device__ __forceinline__ uint32_t pack_h2(float a, float b) {
    __half2 h = __floats2half2_rn(a, b);
    return *(uint32_t*)&h;
}
__device__ __forceinline__ void lds128(uint4& v, uint32_t addr) {
    asm volatile("ld.shared.v4.u32 {%0,%1,%2,%3}, [%4];"
                 : "=r"(v.x), "=r"(v.y), "=r"(v.z), "=r"(v.w) : "r"(addr));
}
__device__ __forceinline__ void mma_fp16(float* c, const uint4& a, uint32_t b0, uint32_t b1) {
    asm volatile(
        "mma.sync.aligned.m16n8k16.row.col.f32.f16.f16.f32 "
        "{%0,%1,%2,%3},{%4,%5,%6,%7},{%8,%9},{%0,%1,%2,%3};"
        : "+f"(c[0]), "+f"(c[1]), "+f"(c[2]), "+f"(c[3])
        : "r"(a.x), "r"(a.y), "r"(a.z), "r"(a.w), "r"(b0), "r"(b1));
}
__device__ __forceinline__ void cp_async16(uint32_t dst, const void* src) {
    asm volatile("cp.async.cg.shared.global [%0], [%1], 16;" :: "r"(dst), "l"(src) : "memory");
}
#define CP_COMMIT() asm volatile("cp.async.commit_group;" ::: "memory")
#define CP_WAIT1()  asm volatile("cp.async.wait_group 1;" ::: "memory")

// ---------------------------------------------------------------------------
// Kernel 0: zero scale accumulator
// ---------------------------------------------------------------------------
__global__ void zero_scale_kernel() { if (threadIdx.x == 0) g_scale_i = 0; }

// ---------------------------------------------------------------------------
// Pack kernels: fp32 [rows, DIN] -> fp16 fragment order (one uint4 per thread)
// t -> lane(32), blk16(8), kstep(4), chunk(32), tile
// A frag: r = blk*16 + lane>>2, c = (lane&3)*2, k0 = chunk*64 + kstep*16
//   {A[r,k0+c..+1], A[r+8,k0+c..+1], A[r,k0+8+c..+1], A[r+8,k0+8+c..+1]}
// B frag (n16 = two n8): n = blk*16 + lane>>2 (lo n8), n+8 (hi n8)
//   {B[n,k0+c..], B[n,k0+8+c..], B[n+8,k0+c..], B[n+8,k0+8+c..]}
// ---------------------------------------------------------------------------
__global__ __launch_bounds__(256) void pack_A_kernel(
    const float* __restrict__ src, uint4* __restrict__ dst)
{
    int t    = blockIdx.x * 256 + threadIdx.x;
    int lane = t & 31;
    int blk  = (t >> 5) & 7;
    int ks   = (t >> 8) & 3;
    int c    = (t >> 10) & 31;
    int tile = t >> 15;
    int gr = tile * 128 + blk * 16 + (lane >> 2);
    int gk = c * 64 + ks * 16 + (lane & 3) * 2;
    const float* p0 = src + (size_t)gr * DINc + gk;
    const float* p1 = p0 + 8 * DINc;
    uint4 v;
    v.x = pack_h2(p0[0], p0[1]);
    v.y = pack_h2(p1[0], p1[1]);
    v.z = pack_h2(p0[8], p0[9]);
    v.w = pack_h2(p1[8], p1[9]);
    dst[t] = v;
}
__global__ __launch_bounds__(256) void pack_B_kernel(
    const float* __restrict__ src, uint4* __restrict__ dst)
{
    int t    = blockIdx.x * 256 + threadIdx.x;
    int lane = t & 31;
    int blk  = (t >> 5) & 7;
    int ks   = (t >> 8) & 3;
    int c    = (t >> 10) & 31;
    int tile = t >> 15;
    int gn = tile * 128 + blk * 16 + (lane >> 2);
    int gk = c * 64 + ks * 16 + (lane & 3) * 2;
    const float* p0 = src + (size_t)gn * DINc + gk;
    const float* p1 = p0 + 8 * DINc;
    uint4 v;
    v.x = pack_h2(p0[0], p0[1]);
    v.y = pack_h2(p0[8], p0[9]);
    v.z = pack_h2(p1[0], p1[1]);
    v.w = pack_h2(p1[8], p1[9]);
    dst[t] = v;
}

// ---------------------------------------------------------------------------
// Kernel 1: single-pass fp16 m16n8k16 GEMM   C = x @ W^T + b
// 128x128 tile, 16 warps (4x4, each 32x32), 3-stage cp.async pipeline.
// ---------------------------------------------------------------------------
__global__ __launch_bounds__(512) void gemm_fp16_kernel(
    const float* __restrict__ bias, float* __restrict__ C)
{
    extern __shared__ char smem[];
    const uint32_t sbase = smem_u32(smem);
    const int tid    = threadIdx.x;
    const int lane   = tid & 31;
    const int wid    = tid >> 5;
    const int warp_m = wid >> 2;      // 0..3 -> rows *32
    const int warp_n = wid & 3;       // 0..3 -> cols *32
    const int bx = blockIdx.x, by = blockIdx.y;

    const uint4* gA = g_fA + (size_t)by * NCHUNK * FRAGS_PER_CHUNK;
    const uint4* gB = g_fB + (size_t)bx * NCHUNK * FRAGS_PER_CHUNK;

    float acc[2][4][4];
    #pragma unroll
    for (int i = 0; i < 2; i++)
        #pragma unroll
        for (int j = 0; j < 4; j++)
            #pragma unroll
            for (int k = 0; k < 4; k++) acc[i][j][k] = 0.0f;

    auto load_chunk = [&](int c, int st) {
        const uint32_t base = sbase + st * STAGE_B;
        const uint4* sA = gA + c * FRAGS_PER_CHUNK;
        const uint4* sB = gB + c * FRAGS_PER_CHUNK;
        #pragma unroll
        for (int p = 0; p < 2; p++) {
            int idx = p * 512 + tid;
            cp_async16(base + idx * 16, sA + idx);
            cp_async16(base + ACH_B + idx * 16, sB + idx);
        }
        CP_COMMIT();
    };

    auto compute = [&](int st) {
        const uint32_t sa = sbase + st * STAGE_B;
        const uint32_t sb = sa + ACH_B;
        #pragma unroll
        for (int ks = 0; ks < 4; ks++) {
            uint4 va[2], vb[2];
            #pragma unroll
            for (int mt = 0; mt < 2; mt++)
                lds128(va[mt], sa + ((ks * 8 + warp_m * 2 + mt) * 32 + lane) * 16);
            #pragma unroll
            for (int j = 0; j < 2; j++)
                lds128(vb[j], sb + ((ks * 8 + warp_n * 2 + j) * 32 + lane) * 16);
            #pragma unroll
            for (int mt = 0; mt < 2; mt++)
                #pragma unroll
                for (int j = 0; j < 2; j++) {
                    mma_fp16(acc[mt][2 * j],     va[mt], vb[j].x, vb[j].y);
                    mma_fp16(acc[mt][2 * j + 1], va[mt], vb[j].z, vb[j].w);
                }
        }
    };

    load_chunk(0, 0);
    load_chunk(1, 1);
    for (int c = 0; c < NCHUNK; c++) {
        CP_WAIT1();            // chunk c resident
        __syncthreads();
        if (c + 2 < NCHUNK) load_chunk(c + 2, (c + 2) % NSTAGE);
        compute(c % NSTAGE);
        __syncthreads();       // stage reusable next iteration
    }

    // Epilogue: c0/c1 at (row, 2*(lane&3)), c2/c3 at row+8
    const int row0 = by * TM + warp_m * 32;
    const int col0 = bx * TN + warp_n * 32;
    #pragma unroll
    for (int mt = 0; mt < 2; mt++) {
        int r = row0 + mt * 16 + (lane >> 2);
        #pragma unroll
        for (int nt = 0; nt < 4; nt++) {
            int cc = col0 + nt * 8 + (lane & 3) * 2;
            float b0 = bias[cc], b1 = bias[cc + 1];
            const float* a = acc[mt][nt];
            *(float2*)(C + (size_t)r * Hc + cc)       = make_float2(a[0] + b0, a[1] + b1);
            *(float2*)(C + (size_t)(r + 8) * Hc + cc) = make_float2(a[2] + b0, a[3] + b1);
        }
    }
}

// ---------------------------------------------------------------------------
// Kernel 2: parallel abs-max over Hs = base[:, anchors, :E]
// 16384 values, 64 blocks, atomicMax on nonneg float bits.
// ---------------------------------------------------------------------------
__global__ __launch_bounds__(256) void absmax_kernel(const float* __restrict__ C)
{
    __shared__ int red[8];
    int i    = blockIdx.x * 256 + threadIdx.x;   // 0..16383
    int b    = i >> 12;
    int rest = i & 4095;
    int a    = rest >> 3;
    int e    = rest & 7;
    int t    = a * 4 + 3;
    float v  = fabsf(C[((size_t)(b * Tc + t)) * Hc + e]);
    int m = __float_as_int(v);
    #pragma unroll
    for (int s = 16; s > 0; s >>= 1)
        m = max(m, __shfl_xor_sync(0xFFFFFFFF, m, s));
    if ((threadIdx.x & 31) == 0) red[threadIdx.x >> 5] = m;
    __syncthreads();
    if (threadIdx.x == 0) {
        #pragma unroll
        for (int w = 1; w < 8; w++) m = max(m, red[w]);
        atomicMax(&g_scale_i, m);
    }
}

// ---------------------------------------------------------------------------
// Kernel 3: softmax / top-2 soft mask / w @ LiMEs -> g_pmix
// ---------------------------------------------------------------------------
__global__ __launch_bounds__(256) void pmix_kernel(
    const float* __restrict__ C, const float* __restrict__ L)
{
    __shared__ float sL[Ec * RANKc];
    for (int i = threadIdx.x; i < Ec * RANKc; i += 256) sL[i] = L[i];
    __syncthreads();

    int idx = blockIdx.x * 256 + threadIdx.x;
    int b   = idx >> 9;
    int a   = idx & (NANCH - 1);
    int t   = a * 4 + 3;
    const float* h = C + ((size_t)(b * Tc + t)) * Hc;

    float inv_scale = 1.0f / fmaxf(__int_as_float(g_scale_i), 1e-6f);

    float l[Ec], lmax = -1e30f;
    #pragma unroll
    for (int e = 0; e < Ec; e++) {
        l[e] = h[e] * inv_scale;
        lmax = fmaxf(lmax, l[e]);
    }
    float p[Ec], s = 0.0f;
    #pragma unroll
    for (int e = 0; e < Ec; e++) { p[e] = expf(l[e] - lmax); s += p[e]; }
    float invs = 1.0f / s;
    #pragma unroll
    for (int e = 0; e < Ec; e++) p[e] *= invs;

    float m1 = -1e30f, m2 = -1e30f;
    #pragma unroll
    for (int e = 0; e < Ec; e++) {
        float v = p[e];
        if (v > m1) { m2 = m1; m1 = v; }
        else if (v > m2) { m2 = v; }
    }
    float w[Ec], ws = 0.0f;
    #pragma unroll
    for (int e = 0; e < Ec; e++) {
        float mask = 1.0f / (1.0f + expf(-(p[e] - m2) * 2.0f));
        w[e] = p[e] * mask;
        ws  += w[e];
    }
    float invws = 1.0f / (ws + 1e-9f);

    float* out = g_pmix + (size_t)idx * RANKc;
    #pragma unroll 8
    for (int r = 0; r < RANKc; r++) {
        float acc = 0.0f;
        #pragma unroll
        for (int e = 0; e < Ec; e++) acc += w[e] * sL[e * RANKc + r];
        out[r] = acc * invws;
    }
}

// ---------------------------------------------------------------------------
// Kernel 4: out[..., :RANK] *= (1 + SCALING * p_mix_full)
// ---------------------------------------------------------------------------
__global__ __launch_bounds__(256) void apply_kernel(float* __restrict__ C)
{
    int idx = blockIdx.x * blockDim.x + threadIdx.x;
    int r4  = idx & 15;
    int tg  = idx >> 4;
    int t   = tg & (Tc - 1);
    int b   = tg >> 11;
    int a   = t >> 2;

    const float4 p = ((const float4*)g_pmix)[((b << 9) + a) * 16 + r4];
    float4* cp = (float4*)(C + (size_t)tg * Hc) + r4;
    float4 v = *cp;
    v.x *= 1.0f + SCALING * p.x;
    v.y *= 1.0f + SCALING * p.y;
    v.z *= 1.0f + SCALING * p.z;
    v.w *= 1.0f + SCALING * p.w;
    *cp = v;
}

// ---------------------------------------------------------------------------
extern "C" void kernel_launch(void* const* d_in, const int* in_sizes, int n_in,
                              void* d_out, int out_size)
{
    const float* x = (const float*)d_in[0];   // [B*T, DIN]
    const float* W = (const float*)d_in[1];   // [H, DIN]
    const float* b = (const float*)d_in[2];   // [H]
    const float* L = (const float*)d_in[3];   // [E, RANK]
    float* out = (float*)d_out;

    cudaFuncSetAttribute(gemm_fp16_kernel,
                         cudaFuncAttributeMaxDynamicSharedMemorySize, SMEM_TOTAL);

    uint4* fA_p; cudaGetSymbolAddress((void**)&fA_p, g_fA);
    uint4* fB_p; cudaGetSymbolAddress((void**)&fB_p, g_fB);

    zero_scale_kernel<<<1, 32>>>();
    pack_A_kernel<<<(MTILES * NCHUNK * FRAGS_PER_CHUNK) / 256, 256>>>(x, fA_p);
    pack_B_kernel<<<(NTILES * NCHUNK * FRAGS_PER_CHUNK) / 256, 256>>>(W, fB_p);

    dim3 grid(NTILES, MTILES);   // (16, 64)
    gemm_fp16_kernel<<<grid, 512, SMEM_TOTAL>>>(b, out);
    absmax_kernel<<<64, 256>>>(out);
    pmix_kernel<<<(Bc * NANCH) / 256, 256>>>(out, L);
    apply_kernel<<<(Bc * Tc * 16) / 256, 256>>>(out);
}

// round 7
// speedup vs baseline: 7.3216x; 1.0111x over previous
#include <cuda_runtime.h>
#include <cuda_fp16.h>
#include <cstdint>

// Problem constants
#define Bc    4
#define Tc    2048
#define DINc  2048
#define Hc    2048
#define Ec    8
#define RANKc 64
#define NANCH 512
#define SCALING 0.25f

// GEMM tiling
#define TM 128
#define TN 128
#define KC 64                          // fp32 K per chunk
#define NCHUNK (DINc / KC)             // 32
#define MTILES ((Bc * Tc) / TM)        // 64
#define NTILES (Hc / TN)               // 16
#define FRAGS_PER_CHUNK 1024           // (4 ksteps)*(8 blk16)*(32 lanes) uint4 frags
#define ACH_B  (FRAGS_PER_CHUNK * 16)  // 16384 bytes per operand per chunk
#define STAGE_B (2 * ACH_B)            // 32768
#define NSTAGE 3
#define SMEM_TOTAL (NSTAGE * STAGE_B)  // 98304

__device__ int g_scale_i;
__device__ __align__(16) float g_pmix[Bc * NANCH * RANKc];
// Fragment-ordered fp16 copies: A 32MB, B 8MB
__device__ __align__(16) uint4 g_fA[(size_t)MTILES * NCHUNK * FRAGS_PER_CHUNK];
__device__ __align__(16) uint4 g_fB[(size_t)NTILES * NCHUNK * FRAGS_PER_CHUNK];

// ---------------------------------------------------------------------------
// Helpers
// ---------------------------------------------------------------------------
__device__ __forceinline__ uint32_t smem_u32(const void* p) {
    uint32_t a;
    asm("{ .reg .u64 t; cvta.to.shared.u64 t, %1; cvt.u32.u64 %0, t; }" : "=r"(a) : "l"(p));
    return a;
}
__device__ __forceinline__ uint32_t pack_h2(float a, float b) {
    __half2 h = __floats2half2_rn(a, b);
    return *(uint32_t*)&h;
}
__device__ __forceinline__ void lds128(uint4& v, uint32_t addr) {
    asm volatile("ld.shared.v4.u32 {%0,%1,%2,%3}, [%4];"
                 : "=r"(v.x), "=r"(v.y), "=r"(v.z), "=r"(v.w) : "r"(addr));
}
__device__ __forceinline__ void mma_fp16(float* c, const uint4& a, uint32_t b0, uint32_t b1) {
    asm volatile(
        "mma.sync.aligned.m16n8k16.row.col.f32.f16.f16.f32 "
        "{%0,%1,%2,%3},{%4,%5,%6,%7},{%8,%9},{%0,%1,%2,%3};"
        : "+f"(c[0]), "+f"(c[1]), "+f"(c[2]), "+f"(c[3])
        : "r"(a.x), "r"(a.y), "r"(a.z), "r"(a.w), "r"(b0), "r"(b1));
}
__device__ __forceinline__ void cp_async16(uint32_t dst, const void* src) {
    asm volatile("cp.async.cg.shared.global [%0], [%1], 16;" :: "r"(dst), "l"(src) : "memory");
}
#define CP_COMMIT() asm volatile("cp.async.commit_group;" ::: "memory")
#define CP_WAIT1()  asm volatile("cp.async.wait_group 1;" ::: "memory")

// ---------------------------------------------------------------------------
// Kernel 0: zero scale accumulator
// ---------------------------------------------------------------------------
__global__ void zero_scale_kernel() { if (threadIdx.x == 0) g_scale_i = 0; }

// ---------------------------------------------------------------------------
// Pack kernels: fp32 [rows, DIN] -> fp16 fragment order (one uint4 per thread)
// t -> lane(32), blk16(8), kstep(4), chunk(32), tile
// ---------------------------------------------------------------------------
__global__ __launch_bounds__(256) void pack_A_kernel(
    const float* __restrict__ src, uint4* __restrict__ dst)
{
    int t    = blockIdx.x * 256 + threadIdx.x;
    int lane = t & 31;
    int blk  = (t >> 5) & 7;
    int ks   = (t >> 8) & 3;
    int c    = (t >> 10) & 31;
    int tile = t >> 15;
    int gr = tile * 128 + blk * 16 + (lane >> 2);
    int gk = c * 64 + ks * 16 + (lane & 3) * 2;
    const float* p0 = src + (size_t)gr * DINc + gk;
    const float* p1 = p0 + 8 * DINc;
    uint4 v;
    v.x = pack_h2(p0[0], p0[1]);
    v.y = pack_h2(p1[0], p1[1]);
    v.z = pack_h2(p0[8], p0[9]);
    v.w = pack_h2(p1[8], p1[9]);
    dst[t] = v;
}
__global__ __launch_bounds__(256) void pack_B_kernel(
    const float* __restrict__ src, uint4* __restrict__ dst)
{
    int t    = blockIdx.x * 256 + threadIdx.x;
    int lane = t & 31;
    int blk  = (t >> 5) & 7;
    int ks   = (t >> 8) & 3;
    int c    = (t >> 10) & 31;
    int tile = t >> 15;
    int gn = tile * 128 + blk * 16 + (lane >> 2);
    int gk = c * 64 + ks * 16 + (lane & 3) * 2;
    const float* p0 = src + (size_t)gn * DINc + gk;
    const float* p1 = p0 + 8 * DINc;
    uint4 v;
    v.x = pack_h2(p0[0], p0[1]);
    v.y = pack_h2(p0[8], p0[9]);
    v.z = pack_h2(p1[0], p1[1]);
    v.w = pack_h2(p1[8], p1[9]);
    dst[t] = v;
}

// ---------------------------------------------------------------------------
// Kernel 1: single-pass fp16 m16n8k16 GEMM   C = x @ W^T + b
// 128x128 tile, 8 warps (2x4, each 64x32), 3-stage cp.async pipeline,
// 2 CTAs per SM.
// ---------------------------------------------------------------------------
__global__ __launch_bounds__(256, 2) void gemm_fp16_kernel(
    const float* __restrict__ bias, float* __restrict__ C)
{
    extern __shared__ char smem[];
    const uint32_t sbase = smem_u32(smem);
    const int tid    = threadIdx.x;
    const int lane   = tid & 31;
    const int wid    = tid >> 5;
    const int warp_m = wid >> 2;      // 0..1 -> rows *64
    const int warp_n = wid & 3;       // 0..3 -> cols *32
    const int bx = blockIdx.x, by = blockIdx.y;

    const uint4* gA = g_fA + (size_t)by * NCHUNK * FRAGS_PER_CHUNK;
    const uint4* gB = g_fB + (size_t)bx * NCHUNK * FRAGS_PER_CHUNK;

    float acc[4][4][4];
    #pragma unroll
    for (int i = 0; i < 4; i++)
        #pragma unroll
        for (int j = 0; j < 4; j++)
            #pragma unroll
            for (int k = 0; k < 4; k++) acc[i][j][k] = 0.0f;

    auto load_chunk = [&](int c, int st) {
        const uint32_t base = sbase + st * STAGE_B;
        const uint4* sA = gA + c * FRAGS_PER_CHUNK;
        const uint4* sB = gB + c * FRAGS_PER_CHUNK;
        #pragma unroll
        for (int p = 0; p < 4; p++) {
            int idx = p * 256 + tid;
            cp_async16(base + idx * 16, sA + idx);
            cp_async16(base + ACH_B + idx * 16, sB + idx);
        }
        CP_COMMIT();
    };

    auto compute = [&](int st) {
        const uint32_t sa = sbase + st * STAGE_B;
        const uint32_t sb = sa + ACH_B;
        #pragma unroll
        for (int ks = 0; ks < 4; ks++) {
            uint4 va[4], vb[2];
            #pragma unroll
            for (int mt = 0; mt < 4; mt++)
                lds128(va[mt], sa + ((ks * 8 + warp_m * 4 + mt) * 32 + lane) * 16);
            #pragma unroll
            for (int j = 0; j < 2; j++)
                lds128(vb[j], sb + ((ks * 8 + warp_n * 2 + j) * 32 + lane) * 16);
            #pragma unroll
            for (int mt = 0; mt < 4; mt++)
                #pragma unroll
                for (int j = 0; j < 2; j++) {
                    mma_fp16(acc[mt][2 * j],     va[mt], vb[j].x, vb[j].y);
                    mma_fp16(acc[mt][2 * j + 1], va[mt], vb[j].z, vb[j].w);
                }
        }
    };

    load_chunk(0, 0);
    load_chunk(1, 1);
    for (int c = 0; c < NCHUNK; c++) {
        CP_WAIT1();            // chunk c resident
        __syncthreads();
        if (c + 2 < NCHUNK) load_chunk(c + 2, (c + 2) % NSTAGE);
        compute(c % NSTAGE);
        __syncthreads();       // stage reusable next iteration
    }

    // Epilogue
    const int row0 = by * TM + warp_m * 64;
    const int col0 = bx * TN + warp_n * 32;
    #pragma unroll
    for (int mt = 0; mt < 4; mt++) {
        int r = row0 + mt * 16 + (lane >> 2);
        #pragma unroll
        for (int nt = 0; nt < 4; nt++) {
            int cc = col0 + nt * 8 + (lane & 3) * 2;
            float b0 = bias[cc], b1 = bias[cc + 1];
            const float* a = acc[mt][nt];
            *(float2*)(C + (size_t)r * Hc + cc)       = make_float2(a[0] + b0, a[1] + b1);
            *(float2*)(C + (size_t)(r + 8) * Hc + cc) = make_float2(a[2] + b0, a[3] + b1);
        }
    }
}

// ---------------------------------------------------------------------------
// Kernel 2: parallel abs-max over Hs = base[:, anchors, :E]
// ---------------------------------------------------------------------------
__global__ __launch_bounds__(256) void absmax_kernel(const float* __restrict__ C)
{
    __shared__ int red[8];
    int i    = blockIdx.x * 256 + threadIdx.x;   // 0..16383
    int b    = i >> 12;
    int rest = i & 4095;
    int a    = rest >> 3;
    int e    = rest & 7;
    int t    = a * 4 + 3;
    float v  = fabsf(C[((size_t)(b * Tc + t)) * Hc + e]);
    int m = __float_as_int(v);
    #pragma unroll
    for (int s = 16; s > 0; s >>= 1)
        m = max(m, __shfl_xor_sync(0xFFFFFFFF, m, s));
    if ((threadIdx.x & 31) == 0) red[threadIdx.x >> 5] = m;
    __syncthreads();
    if (threadIdx.x == 0) {
        #pragma unroll
        for (int w = 1; w < 8; w++) m = max(m, red[w]);
        atomicMax(&g_scale_i, m);
    }
}

// ---------------------------------------------------------------------------
// Kernel 3: softmax / top-2 soft mask / w @ LiMEs -> g_pmix
// ---------------------------------------------------------------------------
__global__ __launch_bounds__(256) void pmix_kernel(
    const float* __restrict__ C, const float* __restrict__ L)
{
    __shared__ float sL[Ec * RANKc];
    for (int i = threadIdx.x; i < Ec * RANKc; i += 256) sL[i] = L[i];
    __syncthreads();

    int idx = blockIdx.x * 256 + threadIdx.x;
    int b   = idx >> 9;
    int a   = idx & (NANCH - 1);
    int t   = a * 4 + 3;
    const float* h = C + ((size_t)(b * Tc + t)) * Hc;

    float inv_scale = 1.0f / fmaxf(__int_as_float(g_scale_i), 1e-6f);

    float l[Ec], lmax = -1e30f;
    #pragma unroll
    for (int e = 0; e < Ec; e++) {
        l[e] = h[e] * inv_scale;
        lmax = fmaxf(lmax, l[e]);
    }
    float p[Ec], s = 0.0f;
    #pragma unroll
    for (int e = 0; e < Ec; e++) { p[e] = expf(l[e] - lmax); s += p[e]; }
    float invs = 1.0f / s;
    #pragma unroll
    for (int e = 0; e < Ec; e++) p[e] *= invs;

    float m1 = -1e30f, m2 = -1e30f;
    #pragma unroll
    for (int e = 0; e < Ec; e++) {
        float v = p[e];
        if (v > m1) { m2 = m1; m1 = v; }
        else if (v > m2) { m2 = v; }
    }
    float w[Ec], ws = 0.0f;
    #pragma unroll
    for (int e = 0; e < Ec; e++) {
        float mask = 1.0f / (1.0f + expf(-(p[e] - m2) * 2.0f));
        w[e] = p[e] * mask;
        ws  += w[e];
    }
    float invws = 1.0f / (ws + 1e-9f);

    float* out = g_pmix + (size_t)idx * RANKc;
    #pragma unroll 8
    for (int r = 0; r < RANKc; r++) {
        float acc = 0.0f;
        #pragma unroll
        for (int e = 0; e < Ec; e++) acc += w[e] * sL[e * RANKc + r];
        out[r] = acc * invws;
    }
}

// ---------------------------------------------------------------------------
// Kernel 4: out[..., :RANK] *= (1 + SCALING * p_mix_full)
// ---------------------------------------------------------------------------
__global__ __launch_bounds__(256) void apply_kernel(float* __restrict__ C)
{
    int idx = blockIdx.x * blockDim.x + threadIdx.x;
    int r4  = idx & 15;
    int tg  = idx >> 4;
    int t   = tg & (Tc - 1);
    int b   = tg >> 11;
    int a   = t >> 2;

    const float4 p = ((const float4*)g_pmix)[((b << 9) + a) * 16 + r4];
    float4* cp = (float4*)(C + (size_t)tg * Hc) + r4;
    float4 v = *cp;
    v.x *= 1.0f + SCALING * p.x;
    v.y *= 1.0f + SCALING * p.y;
    v.z *= 1.0f + SCALING * p.z;
    v.w *= 1.0f + SCALING * p.w;
    *cp = v;
}

// ---------------------------------------------------------------------------
extern "C" void kernel_launch(void* const* d_in, const int* in_sizes, int n_in,
                              void* d_out, int out_size)
{
    const float* x = (const float*)d_in[0];   // [B*T, DIN]
    const float* W = (const float*)d_in[1];   // [H, DIN]
    const float* b = (const float*)d_in[2];   // [H]
    const float* L = (const float*)d_in[3];   // [E, RANK]
    float* out = (float*)d_out;

    cudaFuncSetAttribute(gemm_fp16_kernel,
                         cudaFuncAttributeMaxDynamicSharedMemorySize, SMEM_TOTAL);

    uint4* fA_p; cudaGetSymbolAddress((void**)&fA_p, g_fA);
    uint4* fB_p; cudaGetSymbolAddress((void**)&fB_p, g_fB);

    zero_scale_kernel<<<1, 32>>>();
    pack_A_kernel<<<(MTILES * NCHUNK * FRAGS_PER_CHUNK) / 256, 256>>>(x, fA_p);
    pack_B_kernel<<<(NTILES * NCHUNK * FRAGS_PER_CHUNK) / 256, 256>>>(W, fB_p);

    dim3 grid(NTILES, MTILES);   // (16, 64)
    gemm_fp16_kernel<<<grid, 256, SMEM_TOTAL>>>(b, out);
    absmax_kernel<<<64, 256>>>(out);
    pmix_kernel<<<(Bc * NANCH) / 256, 256>>>(out, L);
    apply_kernel<<<(Bc * Tc * 16) / 256, 256>>>(out);
}

// round 8
// speedup vs baseline: 7.8498x; 1.0721x over previous
#include <cuda_runtime.h>
#include <cuda_fp16.h>
#include <cstdint>

// Problem constants
#define Bc    4
#define Tc    2048
#define DINc  2048
#define Hc    2048
#define Ec    8
#define RANKc 64
#define NANCH 512
#define SCALING 0.25f

// GEMM tiling
#define TM 128
#define TN 128
#define KC 64                          // fp32 K per chunk
#define NCHUNK (DINc / KC)             // 32
#define MTILES ((Bc * Tc) / TM)        // 64
#define NTILES (Hc / TN)               // 16
#define FRAGS_PER_CHUNK 1024           // (4 ksteps)*(8 blk16)*(32 lanes) uint4 frags
#define ACH_B  (FRAGS_PER_CHUNK * 16)  // 16384 bytes per operand per chunk
#define STAGE_B (2 * ACH_B)            // 32768
#define NSTAGE 3
#define SMEM_TOTAL (NSTAGE * STAGE_B)  // 98304

#define A_PACK_BLOCKS ((MTILES * NCHUNK * FRAGS_PER_CHUNK) / 256)  // 8192
#define B_PACK_BLOCKS ((NTILES * NCHUNK * FRAGS_PER_CHUNK) / 256)  // 2048

__device__ int g_scale_i;
// Fragment-ordered fp16 copies: A 32MB, B 8MB
__device__ __align__(16) uint4 g_fA[(size_t)MTILES * NCHUNK * FRAGS_PER_CHUNK];
__device__ __align__(16) uint4 g_fB[(size_t)NTILES * NCHUNK * FRAGS_PER_CHUNK];

// ---------------------------------------------------------------------------
// Helpers
// ---------------------------------------------------------------------------
__device__ __forceinline__ uint32_t smem_u32(const void* p) {
    uint32_t a;
    asm("{ .reg .u64 t; cvta.to.shared.u64 t, %1; cvt.u32.u64 %0, t; }" : "=r"(a) : "l"(p));
    return a;
}
__device__ __forceinline__ uint32_t pack_h2(float a, float b) {
    __half2 h = __floats2half2_rn(a, b);
    return *(uint32_t*)&h;
}
__device__ __forceinline__ void lds128(uint4& v, uint32_t addr) {
    asm volatile("ld.shared.v4.u32 {%0,%1,%2,%3}, [%4];"
                 : "=r"(v.x), "=r"(v.y), "=r"(v.z), "=r"(v.w) : "r"(addr));
}
__device__ __forceinline__ void mma_fp16(float* c, const uint4& a, uint32_t b0, uint32_t b1) {
    asm volatile(
        "mma.sync.aligned.m16n8k16.row.col.f32.f16.f16.f32 "
        "{%0,%1,%2,%3},{%4,%5,%6,%7},{%8,%9},{%0,%1,%2,%3};"
        : "+f"(c[0]), "+f"(c[1]), "+f"(c[2]), "+f"(c[3])
        : "r"(a.x), "r"(a.y), "r"(a.z), "r"(a.w), "r"(b0), "r"(b1));
}
__device__ __forceinline__ void cp_async16(uint32_t dst, const void* src) {
    asm volatile("cp.async.cg.shared.global [%0], [%1], 16;" :: "r"(dst), "l"(src) : "memory");
}
#define CP_COMMIT() asm volatile("cp.async.commit_group;" ::: "memory")
#define CP_WAIT1()  asm volatile("cp.async.wait_group 1;" ::: "memory")
#define CP_WAIT0()  asm volatile("cp.async.wait_group 0;" ::: "memory")

// ---------------------------------------------------------------------------
// Kernel P: merged pack (A blocks then B blocks) + scale zeroing
// frag index t -> lane(32), blk16(8), kstep(4), chunk(32), tile
// ---------------------------------------------------------------------------
__global__ __launch_bounds__(256) void pack_kernel(
    const float* __restrict__ xA, const float* __restrict__ wB)
{
    if (blockIdx.x == 0 && threadIdx.x == 0) g_scale_i = 0;

    const bool isA = blockIdx.x < A_PACK_BLOCKS;
    int t    = (isA ? blockIdx.x : blockIdx.x - A_PACK_BLOCKS) * 256 + threadIdx.x;
    int lane = t & 31;
    int blk  = (t >> 5) & 7;
    int ks   = (t >> 8) & 3;
    int c    = (t >> 10) & 31;
    int tile = t >> 15;
    int gr = tile * 128 + blk * 16 + (lane >> 2);
    int gk = c * 64 + ks * 16 + (lane & 3) * 2;
    const float* p0 = (isA ? xA : wB) + (size_t)gr * DINc + gk;
    const float* p1 = p0 + 8 * DINc;
    uint4 v;
    if (isA) {
        v.x = pack_h2(p0[0], p0[1]);
        v.y = pack_h2(p1[0], p1[1]);
        v.z = pack_h2(p0[8], p0[9]);
        v.w = pack_h2(p1[8], p1[9]);
        g_fA[t] = v;
    } else {
        v.x = pack_h2(p0[0], p0[1]);
        v.y = pack_h2(p0[8], p0[9]);
        v.z = pack_h2(p1[0], p1[1]);
        v.w = pack_h2(p1[8], p1[9]);
        g_fB[t] = v;
    }
}

// ---------------------------------------------------------------------------
// Kernel 1: single-pass fp16 m16n8k16 GEMM   C = x @ W^T + b
// 128x128 tile, 8 warps (2x4, each 64x32), 3-stage pipeline (1 sync/chunk),
// 2 CTAs per SM. Fused anchor absmax (atomicMax) in epilogue.
// ---------------------------------------------------------------------------
__global__ __launch_bounds__(256, 2) void gemm_fp16_kernel(
    const float* __restrict__ bias, float* __restrict__ C)
{
    extern __shared__ char smem[];
    const uint32_t sbase = smem_u32(smem);
    const int tid    = threadIdx.x;
    const int lane   = tid & 31;
    const int wid    = tid >> 5;
    const int warp_m = wid >> 2;      // 0..1 -> rows *64
    const int warp_n = wid & 3;       // 0..3 -> cols *32
    const int bx = blockIdx.x, by = blockIdx.y;

    const uint4* gA = g_fA + (size_t)by * NCHUNK * FRAGS_PER_CHUNK;
    const uint4* gB = g_fB + (size_t)bx * NCHUNK * FRAGS_PER_CHUNK;

    float acc[4][4][4];
    #pragma unroll
    for (int i = 0; i < 4; i++)
        #pragma unroll
        for (int j = 0; j < 4; j++)
            #pragma unroll
            for (int k = 0; k < 4; k++) acc[i][j][k] = 0.0f;

    auto load_chunk = [&](int c, int st) {
        const uint32_t base = sbase + st * STAGE_B;
        const uint4* sA = gA + c * FRAGS_PER_CHUNK;
        const uint4* sB = gB + c * FRAGS_PER_CHUNK;
        #pragma unroll
        for (int p = 0; p < 4; p++) {
            int idx = p * 256 + tid;
            cp_async16(base + idx * 16, sA + idx);
            cp_async16(base + ACH_B + idx * 16, sB + idx);
        }
        CP_COMMIT();
    };

    auto compute = [&](int st) {
        const uint32_t sa = sbase + st * STAGE_B;
        const uint32_t sb = sa + ACH_B;
        #pragma unroll
        for (int ks = 0; ks < 4; ks++) {
            uint4 va[4], vb[2];
            #pragma unroll
            for (int mt = 0; mt < 4; mt++)
                lds128(va[mt], sa + ((ks * 8 + warp_m * 4 + mt) * 32 + lane) * 16);
            #pragma unroll
            for (int j = 0; j < 2; j++)
                lds128(vb[j], sb + ((ks * 8 + warp_n * 2 + j) * 32 + lane) * 16);
            #pragma unroll
            for (int mt = 0; mt < 4; mt++)
                #pragma unroll
                for (int j = 0; j < 2; j++) {
                    mma_fp16(acc[mt][2 * j],     va[mt], vb[j].x, vb[j].y);
                    mma_fp16(acc[mt][2 * j + 1], va[mt], vb[j].z, vb[j].w);
                }
        }
    };

    load_chunk(0, 0);
    load_chunk(1, 1);
    for (int c = 0; c < NCHUNK; c++) {
        if (c == NCHUNK - 1) { CP_WAIT0(); } else { CP_WAIT1(); }
        __syncthreads();      // also guarantees compute(c-1) done -> stage (c+2)%3 free
        if (c + 2 < NCHUNK) load_chunk(c + 2, (c + 2) % NSTAGE);
        compute(c % NSTAGE);
    }

    // Epilogue + fused anchor absmax
    const int row0 = by * TM + warp_m * 64;
    const int col0 = bx * TN + warp_n * 32;
    float amax = 0.0f;
    const bool scale_zone = (bx == 0) && (warp_n == 0);   // cols 0..7 live in nt==0
    #pragma unroll
    for (int mt = 0; mt < 4; mt++) {
        int r = row0 + mt * 16 + (lane >> 2);
        #pragma unroll
        for (int nt = 0; nt < 4; nt++) {
            int cc = col0 + nt * 8 + (lane & 3) * 2;
            float b0 = bias[cc], b1 = bias[cc + 1];
            const float* a = acc[mt][nt];
            float2 o0 = make_float2(a[0] + b0, a[1] + b1);
            float2 o1 = make_float2(a[2] + b0, a[3] + b1);
            *(float2*)(C + (size_t)r * Hc + cc)       = o0;
            *(float2*)(C + (size_t)(r + 8) * Hc + cc) = o1;
            if (scale_zone && nt == 0) {
                // anchor rows: t % 4 == 3 (row, row+8 share row%4)
                if ((r & 3) == 3) {
                    amax = fmaxf(amax, fmaxf(fabsf(o0.x), fabsf(o0.y)));
                    amax = fmaxf(amax, fmaxf(fabsf(o1.x), fabsf(o1.y)));
                }
            }
        }
    }
    if (scale_zone && (lane & 12) == 12 && amax > 0.0f)
        atomicMax(&g_scale_i, __float_as_int(amax));
}

// ---------------------------------------------------------------------------
// Kernel 2: fused pmix + apply.
// Each block: 16 consecutive (b,t) rows = exactly 4 anchors (same batch).
// Threads 0..3 compute per-anchor softmax/top2/weights; all 256 threads then
// compute pmix on the fly and scale C[..., :64].
// ---------------------------------------------------------------------------
__global__ __launch_bounds__(256) void apply_fused_kernel(
    float* __restrict__ C, const float* __restrict__ L)
{
    __shared__ float sL[Ec * RANKc];
    __shared__ float sw[4][Ec];

    const int tid = threadIdx.x;
    for (int i = tid; i < Ec * RANKc; i += 256) sL[i] = L[i];

    const int tg0 = blockIdx.x * 16;        // first (b*T+t) row
    const int b   = tg0 >> 11;
    const int a0  = (tg0 & (Tc - 1)) >> 2;  // first anchor of this block

    if (tid < 4) {
        const int t = (a0 + tid) * 4 + 3;
        const float* h = C + ((size_t)(b * Tc + t)) * Hc;
        const float inv_scale = 1.0f / fmaxf(__int_as_float(g_scale_i), 1e-6f);

        float l[Ec], lmax = -1e30f;
        #pragma unroll
        for (int e = 0; e < Ec; e++) {
            l[e] = h[e] * inv_scale;
            lmax = fmaxf(lmax, l[e]);
        }
        float p[Ec], s = 0.0f;
        #pragma unroll
        for (int e = 0; e < Ec; e++) { p[e] = expf(l[e] - lmax); s += p[e]; }
        float invs = 1.0f / s;
        #pragma unroll
        for (int e = 0; e < Ec; e++) p[e] *= invs;

        float m1 = -1e30f, m2 = -1e30f;
        #pragma unroll
        for (int e = 0; e < Ec; e++) {
            float v = p[e];
            if (v > m1) { m2 = m1; m1 = v; }
            else if (v > m2) { m2 = v; }
        }
        float w[Ec], ws = 0.0f;
        #pragma unroll
        for (int e = 0; e < Ec; e++) {
            float mask = 1.0f / (1.0f + expf(-(p[e] - m2) * 2.0f));
            w[e] = p[e] * mask;
            ws  += w[e];
        }
        float invws = 1.0f / (ws + 1e-9f);
        #pragma unroll
        for (int e = 0; e < Ec; e++) sw[tid][e] = w[e] * invws;
    }
    __syncthreads();

    const int r4  = tid & 15;          // float4 index within rank dim
    const int tgl = tid >> 4;          // 0..15 local row
    const int al  = tgl >> 2;          // 0..3 local anchor

    float pm[4];
    #pragma unroll
    for (int j = 0; j < 4; j++) {
        int r = r4 * 4 + j;
        float acc = 0.0f;
        #pragma unroll
        for (int e = 0; e < Ec; e++) acc += sw[al][e] * sL[e * RANKc + r];
        pm[j] = acc;
    }

    float4* cp = (float4*)(C + (size_t)(tg0 + tgl) * Hc) + r4;
    float4 v = *cp;
    v.x *= 1.0f + SCALING * pm[0];
    v.y *= 1.0f + SCALING * pm[1];
    v.z *= 1.0f + SCALING * pm[2];
    v.w *= 1.0f + SCALING * pm[3];
    *cp = v;
}

// ---------------------------------------------------------------------------
extern "C" void kernel_launch(void* const* d_in, const int* in_sizes, int n_in,
                              void* d_out, int out_size)
{
    const float* x = (const float*)d_in[0];   // [B*T, DIN]
    const float* W = (const float*)d_in[1];   // [H, DIN]
    const float* b = (const float*)d_in[2];   // [H]
    const float* L = (const float*)d_in[3];   // [E, RANK]
    float* out = (float*)d_out;

    cudaFuncSetAttribute(gemm_fp16_kernel,
                         cudaFuncAttributeMaxDynamicSharedMemorySize, SMEM_TOTAL);

    pack_kernel<<<A_PACK_BLOCKS + B_PACK_BLOCKS, 256>>>(x, W);

    dim3 grid(NTILES, MTILES);   // (16, 64)
    gemm_fp16_kernel<<<grid, 256, SMEM_TOTAL>>>(b, out);

    apply_fused_kernel<<<(Bc * Tc) / 16, 256>>>(out, L);
}

// round 9
// speedup vs baseline: 8.0348x; 1.0236x over previous
#include <cuda_runtime.h>
#include <cuda_fp16.h>
#include <cstdint>

// Problem constants
#define Bc    4
#define Tc    2048
#define DINc  2048
#define Hc    2048
#define Ec    8
#define RANKc 64
#define NANCH 512
#define SCALING 0.25f

// GEMM tiling
#define TM 128
#define TN 128
#define KC 64                          // fp32 K per chunk
#define NCHUNK (DINc / KC)             // 32
#define MTILES ((Bc * Tc) / TM)        // 64
#define NTILES (Hc / TN)               // 16
#define FRAGS_PER_CHUNK 1024           // (4 ksteps)*(8 blk16)*(32 lanes) uint4 frags
#define ACH_B  (FRAGS_PER_CHUNK * 16)  // 16384 bytes per operand per chunk
#define STAGE_B (2 * ACH_B)            // 32768
#define NSTAGE 3
#define SMEM_TOTAL (NSTAGE * STAGE_B)  // 98304

#define PACK_BLOCKS_A (MTILES * NCHUNK)   // 2048
#define PACK_BLOCKS_B (NTILES * NCHUNK)   // 512

__device__ int g_scale_i;
// Fragment-ordered fp16 copies: A 32MB, B 8MB
__device__ __align__(16) uint4 g_fA[(size_t)MTILES * NCHUNK * FRAGS_PER_CHUNK];
__device__ __align__(16) uint4 g_fB[(size_t)NTILES * NCHUNK * FRAGS_PER_CHUNK];

// ---------------------------------------------------------------------------
// Helpers
// ---------------------------------------------------------------------------
__device__ __forceinline__ uint32_t smem_u32(const void* p) {
    uint32_t a;
    asm("{ .reg .u64 t; cvta.to.shared.u64 t, %1; cvt.u32.u64 %0, t; }" : "=r"(a) : "l"(p));
    return a;
}
__device__ __forceinline__ uint32_t pack_h2(float a, float b) {
    __half2 h = __floats2half2_rn(a, b);
    return *(uint32_t*)&h;
}
__device__ __forceinline__ void lds128(uint4& v, uint32_t addr) {
    asm volatile("ld.shared.v4.u32 {%0,%1,%2,%3}, [%4];"
                 : "=r"(v.x), "=r"(v.y), "=r"(v.z), "=r"(v.w) : "r"(addr));
}
__device__ __forceinline__ void mma_fp16(float* c, const uint4& a, uint32_t b0, uint32_t b1) {
    asm volatile(
        "mma.sync.aligned.m16n8k16.row.col.f32.f16.f16.f32 "
        "{%0,%1,%2,%3},{%4,%5,%6,%7},{%8,%9},{%0,%1,%2,%3};"
        : "+f"(c[0]), "+f"(c[1]), "+f"(c[2]), "+f"(c[3])
        : "r"(a.x), "r"(a.y), "r"(a.z), "r"(a.w), "r"(b0), "r"(b1));
}
__device__ __forceinline__ void cp_async16(uint32_t dst, const void* src) {
    asm volatile("cp.async.cg.shared.global [%0], [%1], 16;" :: "r"(dst), "l"(src) : "memory");
}
#define CP_COMMIT() asm volatile("cp.async.commit_group;" ::: "memory")
#define CP_WAIT1()  asm volatile("cp.async.wait_group 1;" ::: "memory")
#define CP_WAIT0()  asm volatile("cp.async.wait_group 0;" ::: "memory")

// ---------------------------------------------------------------------------
// Kernel P: smem-staged pack. One block per (tile, chunk):
//   Phase 1: coalesced float4 row loads -> half2 -> swizzled smem
//   Phase 2: conflict-free smem reads -> coalesced uint4 fragment stores
// Swizzle: word' = (word + (row&7)*4) & 31  -> fragment-read bank = lane.
// ---------------------------------------------------------------------------
__global__ __launch_bounds__(256) void pack_kernel(
    const float* __restrict__ xA, const float* __restrict__ wB)
{
    __shared__ uint32_t sh[128][32];

    if (blockIdx.x == 0 && threadIdx.x == 0) g_scale_i = 0;

    const bool isA  = blockIdx.x < PACK_BLOCKS_A;
    const int blkid = isA ? blockIdx.x : blockIdx.x - PACK_BLOCKS_A;
    const int tile  = blkid >> 5;
    const int chunk = blkid & 31;
    const int tid   = threadIdx.x;

    const float* base = (isA ? xA : wB) + ((size_t)tile * 128) * DINc + chunk * 64;

    #pragma unroll
    for (int p = 0; p < 8; p++) {
        int fi  = p * 256 + tid;        // 0..2047 float4s
        int row = fi >> 4;
        int c4  = fi & 15;
        float4 v = *(const float4*)(base + (size_t)row * DINc + c4 * 4);
        uint32_t h0 = pack_h2(v.x, v.y);
        uint32_t h1 = pack_h2(v.z, v.w);
        int w0 = (c4 * 2 + (row & 7) * 4) & 31;   // even, +1 stays in range
        *(uint2*)&sh[row][w0] = make_uint2(h0, h1);
    }
    __syncthreads();

    uint4* dst = (isA ? g_fA : g_fB) +
                 ((size_t)tile * NCHUNK + chunk) * FRAGS_PER_CHUNK;

    auto rd = [&](int rr, int ww) { return sh[rr][(ww + (rr & 7) * 4) & 31]; };

    #pragma unroll
    for (int p = 0; p < 4; p++) {
        int f    = p * 256 + tid;       // 0..1023 fragments
        int lane = f & 31;
        int blk  = (f >> 5) & 7;
        int ks   = (f >> 8) & 3;
        int r = blk * 16 + (lane >> 2);
        int i = ks * 8 + (lane & 3);
        uint4 v;
        if (isA) {
            v.x = rd(r, i);     v.y = rd(r + 8, i);
            v.z = rd(r, i + 4); v.w = rd(r + 8, i + 4);
        } else {
            v.x = rd(r, i);     v.y = rd(r, i + 4);
            v.z = rd(r + 8, i); v.w = rd(r + 8, i + 4);
        }
        dst[f] = v;
    }
}

// ---------------------------------------------------------------------------
// Kernel 1: single-pass fp16 m16n8k16 GEMM   C = x @ W^T + b
// 128x128 tile, 8 warps (2x4, each 64x32), 3-stage pipeline (1 sync/chunk),
// 2 CTAs per SM. Fused anchor absmax (atomicMax) in epilogue.
// ---------------------------------------------------------------------------
__global__ __launch_bounds__(256, 2) void gemm_fp16_kernel(
    const float* __restrict__ bias, float* __restrict__ C)
{
    extern __shared__ char smem[];
    const uint32_t sbase = smem_u32(smem);
    const int tid    = threadIdx.x;
    const int lane   = tid & 31;
    const int wid    = tid >> 5;
    const int warp_m = wid >> 2;      // 0..1 -> rows *64
    const int warp_n = wid & 3;       // 0..3 -> cols *32
    const int bx = blockIdx.x, by = blockIdx.y;

    const uint4* gA = g_fA + (size_t)by * NCHUNK * FRAGS_PER_CHUNK;
    const uint4* gB = g_fB + (size_t)bx * NCHUNK * FRAGS_PER_CHUNK;

    float acc[4][4][4];
    #pragma unroll
    for (int i = 0; i < 4; i++)
        #pragma unroll
        for (int j = 0; j < 4; j++)
            #pragma unroll
            for (int k = 0; k < 4; k++) acc[i][j][k] = 0.0f;

    auto load_chunk = [&](int c, int st) {
        const uint32_t base = sbase + st * STAGE_B;
        const uint4* sA = gA + c * FRAGS_PER_CHUNK;
        const uint4* sB = gB + c * FRAGS_PER_CHUNK;
        #pragma unroll
        for (int p = 0; p < 4; p++) {
            int idx = p * 256 + tid;
            cp_async16(base + idx * 16, sA + idx);
            cp_async16(base + ACH_B + idx * 16, sB + idx);
        }
        CP_COMMIT();
    };

    auto compute = [&](int st) {
        const uint32_t sa = sbase + st * STAGE_B;
        const uint32_t sb = sa + ACH_B;
        #pragma unroll
        for (int ks = 0; ks < 4; ks++) {
            uint4 va[4], vb[2];
            #pragma unroll
            for (int mt = 0; mt < 4; mt++)
                lds128(va[mt], sa + ((ks * 8 + warp_m * 4 + mt) * 32 + lane) * 16);
            #pragma unroll
            for (int j = 0; j < 2; j++)
                lds128(vb[j], sb + ((ks * 8 + warp_n * 2 + j) * 32 + lane) * 16);
            #pragma unroll
            for (int mt = 0; mt < 4; mt++)
                #pragma unroll
                for (int j = 0; j < 2; j++) {
                    mma_fp16(acc[mt][2 * j],     va[mt], vb[j].x, vb[j].y);
                    mma_fp16(acc[mt][2 * j + 1], va[mt], vb[j].z, vb[j].w);
                }
        }
    };

    load_chunk(0, 0);
    load_chunk(1, 1);
    for (int c = 0; c < NCHUNK; c++) {
        if (c == NCHUNK - 1) { CP_WAIT0(); } else { CP_WAIT1(); }
        __syncthreads();      // also guarantees compute(c-1) done -> stage (c+2)%3 free
        if (c + 2 < NCHUNK) load_chunk(c + 2, (c + 2) % NSTAGE);
        compute(c % NSTAGE);
    }

    // Epilogue + fused anchor absmax
    const int row0 = by * TM + warp_m * 64;
    const int col0 = bx * TN + warp_n * 32;
    float amax = 0.0f;
    const bool scale_zone = (bx == 0) && (warp_n == 0);   // cols 0..7 live in nt==0
    #pragma unroll
    for (int mt = 0; mt < 4; mt++) {
        int r = row0 + mt * 16 + (lane >> 2);
        #pragma unroll
        for (int nt = 0; nt < 4; nt++) {
            int cc = col0 + nt * 8 + (lane & 3) * 2;
            float b0 = bias[cc], b1 = bias[cc + 1];
            const float* a = acc[mt][nt];
            float2 o0 = make_float2(a[0] + b0, a[1] + b1);
            float2 o1 = make_float2(a[2] + b0, a[3] + b1);
            *(float2*)(C + (size_t)r * Hc + cc)       = o0;
            *(float2*)(C + (size_t)(r + 8) * Hc + cc) = o1;
            if (scale_zone && nt == 0) {
                if ((r & 3) == 3) {     // anchor rows: t % 4 == 3
                    amax = fmaxf(amax, fmaxf(fabsf(o0.x), fabsf(o0.y)));
                    amax = fmaxf(amax, fmaxf(fabsf(o1.x), fabsf(o1.y)));
                }
            }
        }
    }
    if (scale_zone && (lane & 12) == 12 && amax > 0.0f)
        atomicMax(&g_scale_i, __float_as_int(amax));
}

// ---------------------------------------------------------------------------
// Kernel 2: fused pmix + apply.
// Each block: 16 consecutive (b,t) rows = exactly 4 anchors (same batch).
// ---------------------------------------------------------------------------
__global__ __launch_bounds__(256) void apply_fused_kernel(
    float* __restrict__ C, const float* __restrict__ L)
{
    __shared__ float sL[Ec * RANKc];
    __shared__ float sw[4][Ec];

    const int tid = threadIdx.x;
    for (int i = tid; i < Ec * RANKc; i += 256) sL[i] = L[i];

    const int tg0 = blockIdx.x * 16;        // first (b*T+t) row
    const int b   = tg0 >> 11;
    const int a0  = (tg0 & (Tc - 1)) >> 2;  // first anchor of this block

    if (tid < 4) {
        const int t = (a0 + tid) * 4 + 3;
        const float* h = C + ((size_t)(b * Tc + t)) * Hc;
        const float inv_scale = 1.0f / fmaxf(__int_as_float(g_scale_i), 1e-6f);

        float l[Ec], lmax = -1e30f;
        #pragma unroll
        for (int e = 0; e < Ec; e++) {
            l[e] = h[e] * inv_scale;
            lmax = fmaxf(lmax, l[e]);
        }
        float p[Ec], s = 0.0f;
        #pragma unroll
        for (int e = 0; e < Ec; e++) { p[e] = expf(l[e] - lmax); s += p[e]; }
        float invs = 1.0f / s;
        #pragma unroll
        for (int e = 0; e < Ec; e++) p[e] *= invs;

        float m1 = -1e30f, m2 = -1e30f;
        #pragma unroll
        for (int e = 0; e < Ec; e++) {
            float v = p[e];
            if (v > m1) { m2 = m1; m1 = v; }
            else if (v > m2) { m2 = v; }
        }
        float w[Ec], ws = 0.0f;
        #pragma unroll
        for (int e = 0; e < Ec; e++) {
            float mask = 1.0f / (1.0f + expf(-(p[e] - m2) * 2.0f));
            w[e] = p[e] * mask;
            ws  += w[e];
        }
        float invws = 1.0f / (ws + 1e-9f);
        #pragma unroll
        for (int e = 0; e < Ec; e++) sw[tid][e] = w[e] * invws;
    }
    __syncthreads();

    const int r4  = tid & 15;          // float4 index within rank dim
    const int tgl = tid >> 4;          // 0..15 local row
    const int al  = tgl >> 2;          // 0..3 local anchor

    float pm[4];
    #pragma unroll
    for (int j = 0; j < 4; j++) {
        int r = r4 * 4 + j;
        float acc = 0.0f;
        #pragma unroll
        for (int e = 0; e < Ec; e++) acc += sw[al][e] * sL[e * RANKc + r];
        pm[j] = acc;
    }

    float4* cp = (float4*)(C + (size_t)(tg0 + tgl) * Hc) + r4;
    float4 v = *cp;
    v.x *= 1.0f + SCALING * pm[0];
    v.y *= 1.0f + SCALING * pm[1];
    v.z *= 1.0f + SCALING * pm[2];
    v.w *= 1.0f + SCALING * pm[3];
    *cp = v;
}

// ---------------------------------------------------------------------------
extern "C" void kernel_launch(void* const* d_in, const int* in_sizes, int n_in,
                              void* d_out, int out_size)
{
    const float* x = (const float*)d_in[0];   // [B*T, DIN]
    const float* W = (const float*)d_in[1];   // [H, DIN]
    const float* b = (const float*)d_in[2];   // [H]
    const float* L = (const float*)d_in[3];   // [E, RANK]
    float* out = (float*)d_out;

    cudaFuncSetAttribute(gemm_fp16_kernel,
                         cudaFuncAttributeMaxDynamicSharedMemorySize, SMEM_TOTAL);

    pack_kernel<<<PACK_BLOCKS_A + PACK_BLOCKS_B, 256>>>(x, W);

    dim3 grid(NTILES, MTILES);   // (16, 64)
    gemm_fp16_kernel<<<grid, 256, SMEM_TOTAL>>>(b, out);

    apply_fused_kernel<<<(Bc * Tc) / 16, 256>>>(out, L);
}

// round 10
// speedup vs baseline: 8.3859x; 1.0437x over previous
#include <cuda_runtime.h>
#include <cuda_fp16.h>
#include <cstdint>

// Problem constants
#define Bc    4
#define Tc    2048
#define DINc  2048
#define Hc    2048
#define Ec    8
#define RANKc 64
#define NANCH 512
#define SCALING 0.25f

// GEMM tiling
#define TM 128
#define TN 128
#define KC 64                          // fp32 K per chunk
#define NCHUNK (DINc / KC)             // 32
#define MTILES ((Bc * Tc) / TM)        // 64
#define NTILES (Hc / TN)               // 16
#define FRAGS_PER_CHUNK 1024           // (4 ksteps)*(8 blk16)*(32 lanes) uint4 frags
#define NITER (NCHUNK * 4)             // 128 ksteps total

#define PACK_BLOCKS_A (MTILES * NCHUNK)   // 2048
#define PACK_BLOCKS_B (NTILES * NCHUNK)   // 512

__device__ int g_scale_i;
// Fragment-ordered fp16 copies: A 32MB, B 8MB
__device__ __align__(16) uint4 g_fA[(size_t)MTILES * NCHUNK * FRAGS_PER_CHUNK];
__device__ __align__(16) uint4 g_fB[(size_t)NTILES * NCHUNK * FRAGS_PER_CHUNK];

// ---------------------------------------------------------------------------
// Helpers
// ---------------------------------------------------------------------------
__device__ __forceinline__ uint32_t pack_h2(float a, float b) {
    __half2 h = __floats2half2_rn(a, b);
    return *(uint32_t*)&h;
}
__device__ __forceinline__ void mma_fp16(float* c, const uint4& a, uint32_t b0, uint32_t b1) {
    asm volatile(
        "mma.sync.aligned.m16n8k16.row.col.f32.f16.f16.f32 "
        "{%0,%1,%2,%3},{%4,%5,%6,%7},{%8,%9},{%0,%1,%2,%3};"
        : "+f"(c[0]), "+f"(c[1]), "+f"(c[2]), "+f"(c[3])
        : "r"(a.x), "r"(a.y), "r"(a.z), "r"(a.w), "r"(b0), "r"(b1));
}

// ---------------------------------------------------------------------------
// Kernel P: smem-staged pack (unchanged from R9 — bandwidth-bound).
// ---------------------------------------------------------------------------
__global__ __launch_bounds__(256) void pack_kernel(
    const float* __restrict__ xA, const float* __restrict__ wB)
{
    __shared__ uint32_t sh[128][32];

    if (blockIdx.x == 0 && threadIdx.x == 0) g_scale_i = 0;

    const bool isA  = blockIdx.x < PACK_BLOCKS_A;
    const int blkid = isA ? blockIdx.x : blockIdx.x - PACK_BLOCKS_A;
    const int tile  = blkid >> 5;
    const int chunk = blkid & 31;
    const int tid   = threadIdx.x;

    const float* base = (isA ? xA : wB) + ((size_t)tile * 128) * DINc + chunk * 64;

    #pragma unroll
    for (int p = 0; p < 8; p++) {
        int fi  = p * 256 + tid;        // 0..2047 float4s
        int row = fi >> 4;
        int c4  = fi & 15;
        float4 v = *(const float4*)(base + (size_t)row * DINc + c4 * 4);
        uint32_t h0 = pack_h2(v.x, v.y);
        uint32_t h1 = pack_h2(v.z, v.w);
        int w0 = (c4 * 2 + (row & 7) * 4) & 31;   // even, +1 stays in range
        *(uint2*)&sh[row][w0] = make_uint2(h0, h1);
    }
    __syncthreads();

    uint4* dst = (isA ? g_fA : g_fB) +
                 ((size_t)tile * NCHUNK + chunk) * FRAGS_PER_CHUNK;

    auto rd = [&](int rr, int ww) { return sh[rr][(ww + (rr & 7) * 4) & 31]; };

    #pragma unroll
    for (int p = 0; p < 4; p++) {
        int f    = p * 256 + tid;       // 0..1023 fragments
        int lane = f & 31;
        int blk  = (f >> 5) & 7;
        int ks   = (f >> 8) & 3;
        int r = blk * 16 + (lane >> 2);
        int i = ks * 8 + (lane & 3);
        uint4 v;
        if (isA) {
            v.x = rd(r, i);     v.y = rd(r + 8, i);
            v.z = rd(r, i + 4); v.w = rd(r + 8, i + 4);
        } else {
            v.x = rd(r, i);     v.y = rd(r, i + 4);
            v.z = rd(r + 8, i); v.w = rd(r + 8, i + 4);
        }
        dst[f] = v;
    }
}

// ---------------------------------------------------------------------------
// Kernel 1: fp16 m16n8k16 GEMM, SMEM-FREE.
// Fragments LDG.128'd straight into registers (gmem layout == lane layout).
// 128x128 tile, 8 warps (2x4, each 64x32), register double-buffered ksteps,
// 2 CTAs per SM, no __syncthreads in mainloop.
// ---------------------------------------------------------------------------
__global__ __launch_bounds__(256, 2) void gemm_fp16_kernel(
    const float* __restrict__ bias, float* __restrict__ C)
{
    const int tid    = threadIdx.x;
    const int lane   = tid & 31;
    const int wid    = tid >> 5;
    const int warp_m = wid >> 2;      // 0..1 -> rows *64
    const int warp_n = wid & 3;       // 0..3 -> cols *32
    const int bx = blockIdx.x, by = blockIdx.y;

    // Per-lane fragment streams: offset advances 256 frags (4KB) per kstep.
    const uint4* pa = g_fA + (size_t)by * NCHUNK * FRAGS_PER_CHUNK
                          + warp_m * 128 + lane;
    const uint4* pb = g_fB + (size_t)bx * NCHUNK * FRAGS_PER_CHUNK
                          + warp_n * 64 + lane;

    float acc[4][4][4];
    #pragma unroll
    for (int i = 0; i < 4; i++)
        #pragma unroll
        for (int j = 0; j < 4; j++)
            #pragma unroll
            for (int k = 0; k < 4; k++) acc[i][j][k] = 0.0f;

    uint4 va[2][4], vb[2][2];
    #pragma unroll
    for (int mt = 0; mt < 4; mt++) va[0][mt] = __ldg(pa + mt * 32);
    #pragma unroll
    for (int j = 0; j < 2; j++)    vb[0][j]  = __ldg(pb + j * 32);

    #pragma unroll 2
    for (int it = 0; it < NITER; it++) {
        const int cur = it & 1, nxt = cur ^ 1;
        if (it + 1 < NITER) {
            const uint4* qa = pa + (size_t)(it + 1) * 256;
            const uint4* qb = pb + (size_t)(it + 1) * 256;
            #pragma unroll
            for (int mt = 0; mt < 4; mt++) va[nxt][mt] = __ldg(qa + mt * 32);
            #pragma unroll
            for (int j = 0; j < 2; j++)    vb[nxt][j]  = __ldg(qb + j * 32);
        }
        #pragma unroll
        for (int mt = 0; mt < 4; mt++)
            #pragma unroll
            for (int j = 0; j < 2; j++) {
                mma_fp16(acc[mt][2 * j],     va[cur][mt], vb[cur][j].x, vb[cur][j].y);
                mma_fp16(acc[mt][2 * j + 1], va[cur][mt], vb[cur][j].z, vb[cur][j].w);
            }
    }

    // Epilogue + fused anchor absmax
    const int row0 = by * TM + warp_m * 64;
    const int col0 = bx * TN + warp_n * 32;
    float amax = 0.0f;
    const bool scale_zone = (bx == 0) && (warp_n == 0);   // cols 0..7 live in nt==0
    #pragma unroll
    for (int mt = 0; mt < 4; mt++) {
        int r = row0 + mt * 16 + (lane >> 2);
        #pragma unroll
        for (int nt = 0; nt < 4; nt++) {
            int cc = col0 + nt * 8 + (lane & 3) * 2;
            float b0 = bias[cc], b1 = bias[cc + 1];
            const float* a = acc[mt][nt];
            float2 o0 = make_float2(a[0] + b0, a[1] + b1);
            float2 o1 = make_float2(a[2] + b0, a[3] + b1);
            *(float2*)(C + (size_t)r * Hc + cc)       = o0;
            *(float2*)(C + (size_t)(r + 8) * Hc + cc) = o1;
            if (scale_zone && nt == 0) {
                if ((r & 3) == 3) {     // anchor rows: t % 4 == 3
                    amax = fmaxf(amax, fmaxf(fabsf(o0.x), fabsf(o0.y)));
                    amax = fmaxf(amax, fmaxf(fabsf(o1.x), fabsf(o1.y)));
                }
            }
        }
    }
    if (scale_zone && (lane & 12) == 12 && amax > 0.0f)
        atomicMax(&g_scale_i, __float_as_int(amax));
}

// ---------------------------------------------------------------------------
// Kernel 2: fused pmix + apply.
// Each block: 16 consecutive (b,t) rows = exactly 4 anchors (same batch).
// ---------------------------------------------------------------------------
__global__ __launch_bounds__(256) void apply_fused_kernel(
    float* __restrict__ C, const float* __restrict__ L)
{
    __shared__ float sL[Ec * RANKc];
    __shared__ float sw[4][Ec];

    const int tid = threadIdx.x;
    for (int i = tid; i < Ec * RANKc; i += 256) sL[i] = L[i];

    const int tg0 = blockIdx.x * 16;        // first (b*T+t) row
    const int b   = tg0 >> 11;
    const int a0  = (tg0 & (Tc - 1)) >> 2;  // first anchor of this block

    if (tid < 4) {
        const int t = (a0 + tid) * 4 + 3;
        const float* h = C + ((size_t)(b * Tc + t)) * Hc;
        const float inv_scale = 1.0f / fmaxf(__int_as_float(g_scale_i), 1e-6f);

        float l[Ec], lmax = -1e30f;
        #pragma unroll
        for (int e = 0; e < Ec; e++) {
            l[e] = h[e] * inv_scale;
            lmax = fmaxf(lmax, l[e]);
        }
        float p[Ec], s = 0.0f;
        #pragma unroll
        for (int e = 0; e < Ec; e++) { p[e] = expf(l[e] - lmax); s += p[e]; }
        float invs = 1.0f / s;
        #pragma unroll
        for (int e = 0; e < Ec; e++) p[e] *= invs;

        float m1 = -1e30f, m2 = -1e30f;
        #pragma unroll
        for (int e = 0; e < Ec; e++) {
            float v = p[e];
            if (v > m1) { m2 = m1; m1 = v; }
            else if (v > m2) { m2 = v; }
        }
        float w[Ec], ws = 0.0f;
        #pragma unroll
        for (int e = 0; e < Ec; e++) {
            float mask = 1.0f / (1.0f + expf(-(p[e] - m2) * 2.0f));
            w[e] = p[e] * mask;
            ws  += w[e];
        }
        float invws = 1.0f / (ws + 1e-9f);
        #pragma unroll
        for (int e = 0; e < Ec; e++) sw[tid][e] = w[e] * invws;
    }
    __syncthreads();

    const int r4  = tid & 15;          // float4 index within rank dim
    const int tgl = tid >> 4;          // 0..15 local row
    const int al  = tgl >> 2;          // 0..3 local anchor

    float pm[4];
    #pragma unroll
    for (int j = 0; j < 4; j++) {
        int r = r4 * 4 + j;
        float acc = 0.0f;
        #pragma unroll
        for (int e = 0; e < Ec; e++) acc += sw[al][e] * sL[e * RANKc + r];
        pm[j] = acc;
    }

    float4* cp = (float4*)(C + (size_t)(tg0 + tgl) * Hc) + r4;
    float4 v = *cp;
    v.x *= 1.0f + SCALING * pm[0];
    v.y *= 1.0f + SCALING * pm[1];
    v.z *= 1.0f + SCALING * pm[2];
    v.w *= 1.0f + SCALING * pm[3];
    *cp = v;
}

// ---------------------------------------------------------------------------
extern "C" void kernel_launch(void* const* d_in, const int* in_sizes, int n_in,
                              void* d_out, int out_size)
{
    const float* x = (const float*)d_in[0];   // [B*T, DIN]
    const float* W = (const float*)d_in[1];   // [H, DIN]
    const float* b = (const float*)d_in[2];   // [H]
    const float* L = (const float*)d_in[3];   // [E, RANK]
    float* out = (float*)d_out;

    pack_kernel<<<PACK_BLOCKS_A + PACK_BLOCKS_B, 256>>>(x, W);

    dim3 grid(NTILES, MTILES);   // (16, 64)
    gemm_fp16_kernel<<<grid, 256>>>(b, out);

    apply_fused_kernel<<<(Bc * Tc) / 16, 256>>>(out, L);
}

// round 11
// speedup vs baseline: 8.5148x; 1.0154x over previous
#include <cuda_runtime.h>
#include <cuda_fp16.h>
#include <cstdint>

// Problem constants
#define Bc    4
#define Tc    2048
#define DINc  2048
#define Hc    2048
#define Ec    8
#define RANKc 64
#define NANCH 512
#define SCALING 0.25f

// GEMM tiling
#define TM 128
#define TN 128
#define KC 64                          // fp32 K per chunk
#define NCHUNK (DINc / KC)             // 32
#define MTILES ((Bc * Tc) / TM)        // 64
#define NTILES (Hc / TN)               // 16
#define FRAGS_PER_CHUNK 1024           // (4 ksteps)*(8 blk16)*(32 lanes) uint4 frags
#define NITER (NCHUNK * 4)             // 128 ksteps total
#define KADV 256                       // frags per kstep

#define PACK_BLOCKS_A (MTILES * NCHUNK)   // 2048
#define PACK_BLOCKS_B (NTILES * NCHUNK)   // 512

__device__ int g_scale_i;
// Fragment-ordered fp16 copies: A 32MB, B 8MB
__device__ __align__(16) uint4 g_fA[(size_t)MTILES * NCHUNK * FRAGS_PER_CHUNK];
__device__ __align__(16) uint4 g_fB[(size_t)NTILES * NCHUNK * FRAGS_PER_CHUNK];

// ---------------------------------------------------------------------------
// Helpers
// ---------------------------------------------------------------------------
__device__ __forceinline__ uint32_t pack_h2(float a, float b) {
    __half2 h = __floats2half2_rn(a, b);
    return *(uint32_t*)&h;
}
__device__ __forceinline__ void mma_fp16(float* c, const uint4& a, uint32_t b0, uint32_t b1) {
    asm volatile(
        "mma.sync.aligned.m16n8k16.row.col.f32.f16.f16.f32 "
        "{%0,%1,%2,%3},{%4,%5,%6,%7},{%8,%9},{%0,%1,%2,%3};"
        : "+f"(c[0]), "+f"(c[1]), "+f"(c[2]), "+f"(c[3])
        : "r"(a.x), "r"(a.y), "r"(a.z), "r"(a.w), "r"(b0), "r"(b1));
}

// ---------------------------------------------------------------------------
// Kernel P: smem-staged pack (bandwidth-bound, unchanged).
// ---------------------------------------------------------------------------
__global__ __launch_bounds__(256) void pack_kernel(
    const float* __restrict__ xA, const float* __restrict__ wB)
{
    __shared__ uint32_t sh[128][32];

    if (blockIdx.x == 0 && threadIdx.x == 0) g_scale_i = 0;

    const bool isA  = blockIdx.x < PACK_BLOCKS_A;
    const int blkid = isA ? blockIdx.x : blockIdx.x - PACK_BLOCKS_A;
    const int tile  = blkid >> 5;
    const int chunk = blkid & 31;
    const int tid   = threadIdx.x;

    const float* base = (isA ? xA : wB) + ((size_t)tile * 128) * DINc + chunk * 64;

    #pragma unroll
    for (int p = 0; p < 8; p++) {
        int fi  = p * 256 + tid;        // 0..2047 float4s
        int row = fi >> 4;
        int c4  = fi & 15;
        float4 v = *(const float4*)(base + (size_t)row * DINc + c4 * 4);
        uint32_t h0 = pack_h2(v.x, v.y);
        uint32_t h1 = pack_h2(v.z, v.w);
        int w0 = (c4 * 2 + (row & 7) * 4) & 31;   // even, +1 stays in range
        *(uint2*)&sh[row][w0] = make_uint2(h0, h1);
    }
    __syncthreads();

    uint4* dst = (isA ? g_fA : g_fB) +
                 ((size_t)tile * NCHUNK + chunk) * FRAGS_PER_CHUNK;

    auto rd = [&](int rr, int ww) { return sh[rr][(ww + (rr & 7) * 4) & 31]; };

    #pragma unroll
    for (int p = 0; p < 4; p++) {
        int f    = p * 256 + tid;       // 0..1023 fragments
        int lane = f & 31;
        int blk  = (f >> 5) & 7;
        int ks   = (f >> 8) & 3;
        int r = blk * 16 + (lane >> 2);
        int i = ks * 8 + (lane & 3);
        uint4 v;
        if (isA) {
            v.x = rd(r, i);     v.y = rd(r + 8, i);
            v.z = rd(r, i + 4); v.w = rd(r + 8, i + 4);
        } else {
            v.x = rd(r, i);     v.y = rd(r, i + 4);
            v.z = rd(r + 8, i); v.w = rd(r + 8, i + 4);
        }
        dst[f] = v;
    }
}

// ---------------------------------------------------------------------------
// Kernel 1: fp16 m16n8k16 GEMM, SMEM-free, register double-buffered.
// Peeled mainloop, constant-increment pointers, 2 ksteps per loop body
// (explicit buffer alternation — no modulo, no tail branch).
// ---------------------------------------------------------------------------
__global__ __launch_bounds__(256, 2) void gemm_fp16_kernel(
    const float* __restrict__ bias, float* __restrict__ C)
{
    const int tid    = threadIdx.x;
    const int lane   = tid & 31;
    const int wid    = tid >> 5;
    const int warp_m = wid >> 2;      // 0..1 -> rows *64
    const int warp_n = wid & 3;       // 0..3 -> cols *32
    const int bx = blockIdx.x, by = blockIdx.y;

    // Per-lane fragment streams; advance KADV frags (4KB) per kstep.
    const uint4* pa = g_fA + (size_t)by * NCHUNK * FRAGS_PER_CHUNK
                          + warp_m * 128 + lane;
    const uint4* pb = g_fB + (size_t)bx * NCHUNK * FRAGS_PER_CHUNK
                          + warp_n * 64 + lane;

    float acc[4][4][4];
    #pragma unroll
    for (int i = 0; i < 4; i++)
        #pragma unroll
        for (int j = 0; j < 4; j++)
            #pragma unroll
            for (int k = 0; k < 4; k++) acc[i][j][k] = 0.0f;

    uint4 va[2][4], vb[2][2];

    // Prologue: load kstep 0 into buffer 0.
    #pragma unroll
    for (int j = 0; j < 2; j++)    vb[0][j]  = __ldg(pb + j * 32);
    #pragma unroll
    for (int mt = 0; mt < 4; mt++) va[0][mt] = __ldg(pa + mt * 32);
    pa += KADV; pb += KADV;

    // Main loop: 63 double-iterations = ksteps 0..125 computed,
    // prefetching 1..126. Buffers alternate explicitly.
    #pragma unroll 1
    for (int it = 0; it < (NITER - 2) / 2; it++) {
        // prefetch kstep (2it+1) -> buf1, compute kstep (2it) from buf0
        #pragma unroll
        for (int j = 0; j < 2; j++)    vb[1][j]  = __ldg(pb + j * 32);
        #pragma unroll
        for (int mt = 0; mt < 4; mt++) va[1][mt] = __ldg(pa + mt * 32);
        pa += KADV; pb += KADV;
        #pragma unroll
        for (int mt = 0; mt < 4; mt++)
            #pragma unroll
            for (int j = 0; j < 2; j++) {
                mma_fp16(acc[mt][2 * j],     va[0][mt], vb[0][j].x, vb[0][j].y);
                mma_fp16(acc[mt][2 * j + 1], va[0][mt], vb[0][j].z, vb[0][j].w);
            }
        // prefetch kstep (2it+2) -> buf0, compute kstep (2it+1) from buf1
        #pragma unroll
        for (int j = 0; j < 2; j++)    vb[0][j]  = __ldg(pb + j * 32);
        #pragma unroll
        for (int mt = 0; mt < 4; mt++) va[0][mt] = __ldg(pa + mt * 32);
        pa += KADV; pb += KADV;
        #pragma unroll
        for (int mt = 0; mt < 4; mt++)
            #pragma unroll
            for (int j = 0; j < 2; j++) {
                mma_fp16(acc[mt][2 * j],     va[1][mt], vb[1][j].x, vb[1][j].y);
                mma_fp16(acc[mt][2 * j + 1], va[1][mt], vb[1][j].z, vb[1][j].w);
            }
    }

    // Epilogue ksteps 126 (prefetch 127) and 127 (no prefetch).
    #pragma unroll
    for (int j = 0; j < 2; j++)    vb[1][j]  = __ldg(pb + j * 32);
    #pragma unroll
    for (int mt = 0; mt < 4; mt++) va[1][mt] = __ldg(pa + mt * 32);
    #pragma unroll
    for (int mt = 0; mt < 4; mt++)
        #pragma unroll
        for (int j = 0; j < 2; j++) {
            mma_fp16(acc[mt][2 * j],     va[0][mt], vb[0][j].x, vb[0][j].y);
            mma_fp16(acc[mt][2 * j + 1], va[0][mt], vb[0][j].z, vb[0][j].w);
        }
    #pragma unroll
    for (int mt = 0; mt < 4; mt++)
        #pragma unroll
        for (int j = 0; j < 2; j++) {
            mma_fp16(acc[mt][2 * j],     va[1][mt], vb[1][j].x, vb[1][j].y);
            mma_fp16(acc[mt][2 * j + 1], va[1][mt], vb[1][j].z, vb[1][j].w);
        }

    // Epilogue + fused anchor absmax
    const int row0 = by * TM + warp_m * 64;
    const int col0 = bx * TN + warp_n * 32;
    float amax = 0.0f;
    const bool scale_zone = (bx == 0) && (warp_n == 0);   // cols 0..7 live in nt==0
    #pragma unroll
    for (int mt = 0; mt < 4; mt++) {
        int r = row0 + mt * 16 + (lane >> 2);
        #pragma unroll
        for (int nt = 0; nt < 4; nt++) {
            int cc = col0 + nt * 8 + (lane & 3) * 2;
            float b0 = bias[cc], b1 = bias[cc + 1];
            const float* a = acc[mt][nt];
            float2 o0 = make_float2(a[0] + b0, a[1] + b1);
            float2 o1 = make_float2(a[2] + b0, a[3] + b1);
            *(float2*)(C + (size_t)r * Hc + cc)       = o0;
            *(float2*)(C + (size_t)(r + 8) * Hc + cc) = o1;
            if (scale_zone && nt == 0) {
                if ((r & 3) == 3) {     // anchor rows: t % 4 == 3
                    amax = fmaxf(amax, fmaxf(fabsf(o0.x), fabsf(o0.y)));
                    amax = fmaxf(amax, fmaxf(fabsf(o1.x), fabsf(o1.y)));
                }
            }
        }
    }
    if (scale_zone && (lane & 12) == 12 && amax > 0.0f)
        atomicMax(&g_scale_i, __float_as_int(amax));
}

// ---------------------------------------------------------------------------
// Kernel 2: fused pmix + apply.
// Each block: 16 consecutive (b,t) rows = exactly 4 anchors (same batch).
// ---------------------------------------------------------------------------
__global__ __launch_bounds__(256) void apply_fused_kernel(
    float* __restrict__ C, const float* __restrict__ L)
{
    __shared__ float sL[Ec * RANKc];
    __shared__ float sw[4][Ec];

    const int tid = threadIdx.x;
    for (int i = tid; i < Ec * RANKc; i += 256) sL[i] = L[i];

    const int tg0 = blockIdx.x * 16;        // first (b*T+t) row
    const int b   = tg0 >> 11;
    const int a0  = (tg0 & (Tc - 1)) >> 2;  // first anchor of this block

    if (tid < 4) {
        const int t = (a0 + tid) * 4 + 3;
        const float* h = C + ((size_t)(b * Tc + t)) * Hc;
        const float inv_scale = 1.0f / fmaxf(__int_as_float(g_scale_i), 1e-6f);

        float l[Ec], lmax = -1e30f;
        #pragma unroll
        for (int e = 0; e < Ec; e++) {
            l[e] = h[e] * inv_scale;
            lmax = fmaxf(lmax, l[e]);
        }
        float p[Ec], s = 0.0f;
        #pragma unroll
        for (int e = 0; e < Ec; e++) { p[e] = expf(l[e] - lmax); s += p[e]; }
        float invs = 1.0f / s;
        #pragma unroll
        for (int e = 0; e < Ec; e++) p[e] *= invs;

        float m1 = -1e30f, m2 = -1e30f;
        #pragma unroll
        for (int e = 0; e < Ec; e++) {
            float v = p[e];
            if (v > m1) { m2 = m1; m1 = v; }
            else if (v > m2) { m2 = v; }
        }
        float w[Ec], ws = 0.0f;
        #pragma unroll
        for (int e = 0; e < Ec; e++) {
            float mask = 1.0f / (1.0f + expf(-(p[e] - m2) * 2.0f));
            w[e] = p[e] * mask;
            ws  += w[e];
        }
        float invws = 1.0f / (ws + 1e-9f);
        #pragma unroll
        for (int e = 0; e < Ec; e++) sw[tid][e] = w[e] * invws;
    }
    __syncthreads();

    const int r4  = tid & 15;          // float4 index within rank dim
    const int tgl = tid >> 4;          // 0..15 local row
    const int al  = tgl >> 2;          // 0..3 local anchor

    float pm[4];
    #pragma unroll
    for (int j = 0; j < 4; j++) {
        int r = r4 * 4 + j;
        float acc = 0.0f;
        #pragma unroll
        for (int e = 0; e < Ec; e++) acc += sw[al][e] * sL[e * RANKc + r];
        pm[j] = acc;
    }

    float4* cp = (float4*)(C + (size_t)(tg0 + tgl) * Hc) + r4;
    float4 v = *cp;
    v.x *= 1.0f + SCALING * pm[0];
    v.y *= 1.0f + SCALING * pm[1];
    v.z *= 1.0f + SCALING * pm[2];
    v.w *= 1.0f + SCALING * pm[3];
    *cp = v;
}

// ---------------------------------------------------------------------------
extern "C" void kernel_launch(void* const* d_in, const int* in_sizes, int n_in,
                              void* d_out, int out_size)
{
    const float* x = (const float*)d_in[0];   // [B*T, DIN]
    const float* W = (const float*)d_in[1];   // [H, DIN]
    const float* b = (const float*)d_in[2];   // [H]
    const float* L = (const float*)d_in[3];   // [E, RANK]
    float* out = (float*)d_out;

    pack_kernel<<<PACK_BLOCKS_A + PACK_BLOCKS_B, 256>>>(x, W);

    dim3 grid(NTILES, MTILES);   // (16, 64)
    gemm_fp16_kernel<<<grid, 256>>>(b, out);

    apply_fused_kernel<<<(Bc * Tc) / 16, 256>>>(out, L);
}